// round 3
// baseline (speedup 1.0000x reference)
#include <cuda_runtime.h>

#define NMAX 50000
#define EMAX 800000
#define C 128

// ---------------- scratch (static device globals; no allocation) ----------------
__device__ int   g_degsrc[NMAX];
__device__ int   g_degdst[NMAX];
__device__ int   g_cursor[NMAX];
__device__ float g_dinv[NMAX];
__device__ int   g_rowptr[NMAX + 1];
__device__ int   g_bsum[64];
__device__ int   g_is64;                 // 1 if edge_index is int64, 0 if int32
__device__ int   g_nsrc[EMAX];
__device__ float g_nw[EMAX];
__device__ __align__(16) float g_T0[NMAX * C];
__device__ __align__(16) float g_T1[NMAX * C];
__device__ __align__(16) float g_T2[NMAX * C];
__device__ __align__(16) float g_Y[(size_t)NMAX * 512];

// device-side buffer selection (avoids cudaGetSymbolAddress on host)
__device__ __forceinline__ const float* sel_buf(int id, const float* x) {
    switch (id) {
        case 0:  return g_T0;
        case 1:  return g_T1;
        case 2:  return g_T2;
        default: return x;
    }
}
__device__ __forceinline__ float* sel_buf_w(int id) {
    switch (id) {
        case 0:  return g_T0;
        case 1:  return g_T1;
        default: return g_T2;
    }
}

// dtype-dispatching edge index load
__device__ __forceinline__ long long load_idx(const void* ei, int is64, size_t pos) {
    if (is64) return ((const long long*)ei)[pos];
    return (long long)((const int*)ei)[pos];
}

// ---------------- dtype detection ----------------
// Interpret first up-to-2048 entries as int64; if ALL lie in [0,N) -> int64 else int32.
__global__ void k_detect(const void* ei, int E, int N) {
    __shared__ int bad;
    if (threadIdx.x == 0) bad = 0;
    __syncthreads();
    int cnt = min(E, 2048);
    for (int i = threadIdx.x; i < cnt; i += blockDim.x) {
        long long v = ((const long long*)ei)[i];
        if (v < 0 || v >= (long long)N) atomicOr(&bad, 1);
    }
    __syncthreads();
    if (threadIdx.x == 0) g_is64 = bad ? 0 : 1;
}

// ---------------- setup kernels ----------------
__global__ void k_zero(int N) {
    int i = blockIdx.x * blockDim.x + threadIdx.x;
    if (i < N) { g_degsrc[i] = 0; g_degdst[i] = 0; g_cursor[i] = 0; }
}

__global__ void k_deg(const void* __restrict__ ei, int E, int N) {
    int e = blockIdx.x * blockDim.x + threadIdx.x;
    if (e < E) {
        int is64 = g_is64;
        long long s = load_idx(ei, is64, e);
        long long d = load_idx(ei, is64, (size_t)E + e);
        if (s >= 0 && s < N) atomicAdd(&g_degsrc[(int)s], 1);
        if (d >= 0 && d < N) atomicAdd(&g_degdst[(int)d], 1);
    }
}

__global__ void k_dinv(int N) {
    int i = blockIdx.x * blockDim.x + threadIdx.x;
    if (i < N) {
        int d = g_degsrc[i];
        g_dinv[i] = (d > 0) ? rsqrtf((float)d) : 0.0f;
    }
}

// exclusive scan of g_degdst -> g_rowptr  (chunked Hillis-Steele + block offsets)
__global__ void k_scan1(int N) {
    __shared__ int sh[1024];
    int tid = threadIdx.x;
    int i = blockIdx.x * 1024 + tid;
    int v = (i < N) ? g_degdst[i] : 0;
    sh[tid] = v;
    __syncthreads();
    for (int off = 1; off < 1024; off <<= 1) {
        int t = (tid >= off) ? sh[tid - off] : 0;
        __syncthreads();
        sh[tid] += t;
        __syncthreads();
    }
    if (i < N) g_rowptr[i] = sh[tid] - v;   // exclusive
    if (tid == 1023) g_bsum[blockIdx.x] = sh[1023];
}

__global__ void k_scan2(int nb, int N) {
    if (threadIdx.x == 0 && blockIdx.x == 0) {
        int run = 0;
        for (int b = 0; b < nb; b++) { int v = g_bsum[b]; g_bsum[b] = run; run += v; }
        g_rowptr[N] = run;
    }
}

__global__ void k_scan3(int N) {
    int i = blockIdx.x * 1024 + threadIdx.x;
    if (i < N) g_rowptr[i] += g_bsum[blockIdx.x];
}

__global__ void k_scatter(const void* __restrict__ ei, int E, int N) {
    int e = blockIdx.x * blockDim.x + threadIdx.x;
    if (e < E) {
        int is64 = g_is64;
        long long sl = load_idx(ei, is64, e);
        long long dl = load_idx(ei, is64, (size_t)E + e);
        if (sl < 0 || sl >= N || dl < 0 || dl >= N) return;
        int s = (int)sl, d = (int)dl;
        // reference: lw = (-dinv[row]*dinv[col]) - 1 for real edges; self-loops -> 0 (skipped)
        float w = -g_dinv[s] * g_dinv[d] - 1.0f;
        int pos = g_rowptr[d] + atomicAdd(&g_cursor[d], 1);
        g_nsrc[pos] = s;
        g_nw[pos]   = w;
    }
}

__global__ void k_yinit(const float* __restrict__ cheb_b, int N) {
    size_t i = (size_t)blockIdx.x * blockDim.x + threadIdx.x;
    size_t total = (size_t)N * 512;
    if (i < total) g_Y[i] = cheb_b[i & 511];
}

// ---------------- propagation: Tout = alpha * (L' @ Tin) + beta * Tsub ----------------
// one 128-thread block per node; thread = channel; neighbor (src,w) staged in smem
__global__ void k_prop(int in_id, int sub_id, int out_id, const float* __restrict__ x,
                       float alpha, float beta, int N) {
    const float* Tin  = sel_buf(in_id, x);
    const float* Tsub = sel_buf(sub_id, x);
    float*       Tout = sel_buf_w(out_id);

    int n = blockIdx.x;
    int c = threadIdx.x;
    int beg = g_rowptr[n], end = g_rowptr[n + 1];
    __shared__ int   ss[64];
    __shared__ float sw[64];
    float acc = 0.0f;
    for (int t0 = beg; t0 < end; t0 += 64) {
        int cnt = min(64, end - t0);
        if (c < cnt) { ss[c] = g_nsrc[t0 + c]; sw[c] = g_nw[t0 + c]; }
        __syncthreads();
        int j = 0;
        for (; j + 4 <= cnt; j += 4) {
            float a0 = Tin[(size_t)ss[j]     * C + c];
            float a1 = Tin[(size_t)ss[j + 1] * C + c];
            float a2 = Tin[(size_t)ss[j + 2] * C + c];
            float a3 = Tin[(size_t)ss[j + 3] * C + c];
            acc += sw[j] * a0;
            acc += sw[j + 1] * a1;
            acc += sw[j + 2] * a2;
            acc += sw[j + 3] * a3;
        }
        for (; j < cnt; ++j) acc += sw[j] * Tin[(size_t)ss[j] * C + c];
        __syncthreads();
    }
    Tout[(size_t)n * C + c] = alpha * acc + beta * Tsub[(size_t)n * C + c];
}

// ---------------- GEMM: Y[:, f*128 : f*128+128] += A(Nx128) @ W_k,f (128x128) ----------
// grid.y enumerates active filters (f = i0 + blockIdx.y); BM=64, BN=128, BK=16
__global__ void k_gemm(int a_id, const float* __restrict__ x,
                       const float* __restrict__ cheb_w,
                       int k, int i0, int N) {
    const float* A = sel_buf(a_id, x);
    int f = i0 + blockIdx.y;
    const float* W = cheb_w + ((size_t)(5 * f * (f + 1) / 2 + k)) * (128 * 128);
    int row0 = blockIdx.x * 64;

    __shared__ float As[64][20];     // padded row (80B, float4-aligned stores)
    __shared__ float Ws[16][128];

    int tid = threadIdx.x;
    int lane = tid & 31, warp = tid >> 5;
    int c0 = lane * 4;               // 4 output cols
    int m0 = warp * 8;               // 8 output rows

    float acc[8][4];
#pragma unroll
    for (int m = 0; m < 8; ++m)
#pragma unroll
        for (int j = 0; j < 4; ++j) acc[m][j] = 0.0f;

    int am = tid >> 2;               // 0..63
    int aq = (tid & 3) * 4;          // 0,4,8,12
    int wr = tid >> 4;               // 0..15
    int wc = (tid & 15) * 8;         // 0..120

    for (int kk0 = 0; kk0 < 128; kk0 += 16) {
        int row = row0 + am;
        float4 av = (row < N) ? *(const float4*)&A[(size_t)row * 128 + kk0 + aq]
                              : make_float4(0.f, 0.f, 0.f, 0.f);
        *(float4*)&As[am][aq] = av;
        float4 w0 = *(const float4*)&W[(size_t)(kk0 + wr) * 128 + wc];
        float4 w1 = *(const float4*)&W[(size_t)(kk0 + wr) * 128 + wc + 4];
        *(float4*)&Ws[wr][wc]     = w0;
        *(float4*)&Ws[wr][wc + 4] = w1;
        __syncthreads();
#pragma unroll
        for (int kk = 0; kk < 16; ++kk) {
            float4 wv = *(float4*)&Ws[kk][c0];
#pragma unroll
            for (int m = 0; m < 8; ++m) {
                float a = As[m0 + m][kk];
                acc[m][0] += a * wv.x;
                acc[m][1] += a * wv.y;
                acc[m][2] += a * wv.z;
                acc[m][3] += a * wv.w;
            }
        }
        __syncthreads();
    }

    int colbase = f * 128 + c0;
#pragma unroll
    for (int m = 0; m < 8; ++m) {
        int row = row0 + m0 + m;
        if (row < N) {
            float4* yp = (float4*)&g_Y[(size_t)row * 512 + colbase];
            float4 y = *yp;
            y.x += acc[m][0]; y.y += acc[m][1]; y.z += acc[m][2]; y.w += acc[m][3];
            *yp = y;
        }
    }
}

// ---------------- attention softmax + combine + layernorm ----------------
__global__ void k_final(const float* __restrict__ attn_w, const float* __restrict__ attn_b,
                        const float* __restrict__ ln_g, const float* __restrict__ ln_b,
                        float* __restrict__ out, int N) {
    int n = blockIdx.x, t = threadIdx.x;
    const float* yr = g_Y + (size_t)n * 512;

    float l[4] = {0.f, 0.f, 0.f, 0.f};
    for (int j = t; j < 512; j += 128) {
        float v = yr[j];
        float4 aw = *(const float4*)&attn_w[j * 4];
        l[0] += v * aw.x; l[1] += v * aw.y; l[2] += v * aw.z; l[3] += v * aw.w;
    }
#pragma unroll
    for (int o = 16; o > 0; o >>= 1) {
        l[0] += __shfl_down_sync(0xffffffffu, l[0], o);
        l[1] += __shfl_down_sync(0xffffffffu, l[1], o);
        l[2] += __shfl_down_sync(0xffffffffu, l[2], o);
        l[3] += __shfl_down_sync(0xffffffffu, l[3], o);
    }
    __shared__ float sr[4][4];
    __shared__ float sa[4];
    __shared__ float rs[4];
    int lane = t & 31, w = t >> 5;
    if (lane == 0) { sr[w][0] = l[0]; sr[w][1] = l[1]; sr[w][2] = l[2]; sr[w][3] = l[3]; }
    __syncthreads();
    if (t == 0) {
        float L[4];
#pragma unroll
        for (int i = 0; i < 4; ++i)
            L[i] = sr[0][i] + sr[1][i] + sr[2][i] + sr[3][i] + attn_b[i];
        float m = fmaxf(fmaxf(L[0], L[1]), fmaxf(L[2], L[3]));
        float e0 = expf(L[0] - m), e1 = expf(L[1] - m), e2 = expf(L[2] - m), e3 = expf(L[3] - m);
        float s = e0 + e1 + e2 + e3;
        sa[0] = e0 / s; sa[1] = e1 / s; sa[2] = e2 / s; sa[3] = e3 / s;
    }
    __syncthreads();

    float cmb = sa[0] * yr[t] + sa[1] * yr[128 + t] + sa[2] * yr[256 + t] + sa[3] * yr[384 + t];

    // mean
    float v = cmb;
#pragma unroll
    for (int o = 16; o > 0; o >>= 1) v += __shfl_down_sync(0xffffffffu, v, o);
    if (lane == 0) rs[w] = v;
    __syncthreads();
    float mu = (rs[0] + rs[1] + rs[2] + rs[3]) * (1.0f / 128.0f);
    __syncthreads();

    // variance (two-pass like reference: mean((c-mu)^2))
    float d = cmb - mu;
    float v2 = d * d;
#pragma unroll
    for (int o = 16; o > 0; o >>= 1) v2 += __shfl_down_sync(0xffffffffu, v2, o);
    if (lane == 0) rs[w] = v2;
    __syncthreads();
    float var = (rs[0] + rs[1] + rs[2] + rs[3]) * (1.0f / 128.0f);
    float inv = rsqrtf(var + 1e-5f);

    out[(size_t)n * 128 + t] = d * inv * ln_g[t] + ln_b[t];
}

// ---------------- host ----------------
extern "C" void kernel_launch(void* const* d_in, const int* in_sizes, int n_in,
                              void* d_out, int out_size) {
    const float* x      = (const float*)d_in[0];
    const void*  ei     = d_in[1];
    const float* cheb_w = (const float*)d_in[2];
    const float* cheb_b = (const float*)d_in[3];
    const float* attn_w = (const float*)d_in[4];
    const float* attn_b = (const float*)d_in[5];
    const float* ln_g   = (const float*)d_in[6];
    const float* ln_b   = (const float*)d_in[7];
    float*       out    = (float*)d_out;

    int N = in_sizes[0] / 128;
    int E = in_sizes[1] / 2;
    if (N > NMAX) N = NMAX;
    if (E > EMAX) E = EMAX;

    // graph structure build (per call; all async on default stream)
    k_detect<<<1, 256>>>(ei, E, N);
    k_zero<<<(N + 255) / 256, 256>>>(N);
    k_deg<<<(E + 255) / 256, 256>>>(ei, E, N);
    k_dinv<<<(N + 255) / 256, 256>>>(N);
    int nb = (N + 1023) / 1024;
    k_scan1<<<nb, 1024>>>(N);
    k_scan2<<<1, 32>>>(nb, N);
    k_scan3<<<nb, 1024>>>(N);
    k_scatter<<<(E + 255) / 256, 256>>>(ei, E, N);

    size_t ytot = (size_t)N * 512;
    k_yinit<<<(unsigned)((ytot + 255) / 256), 256>>>(cheb_b, N);

    // buffer id schedule: id 3 = x; ids 0..2 = g_T0..g_T2 (ring)
    int id[20];
    id[0] = 3;
    for (int k = 1; k < 20; ++k) id[k] = (k - 1) % 3;

    auto launch_gemm = [&](int a_id, int k) {
        int i0 = (k < 5) ? 0 : (k < 10) ? 1 : (k < 15) ? 2 : 3;
        dim3 g((N + 63) / 64, 4 - i0);
        k_gemm<<<g, 256>>>(a_id, x, cheb_w, k, i0, N);
    };

    // k = 0: T0 = x
    launch_gemm(id[0], 0);
    // k = 1: T1 = L' x
    k_prop<<<N, 128>>>(id[0], id[0], id[1], x, 1.0f, 0.0f, N);
    launch_gemm(id[1], 1);
    // k >= 2: Tk = 2 L' T_{k-1} - T_{k-2}
    for (int k = 2; k < 20; ++k) {
        k_prop<<<N, 128>>>(id[k - 1], id[k - 2], id[k], x, 2.0f, -1.0f, N);
        launch_gemm(id[k], k);
    }

    k_final<<<N, 128>>>(attn_w, attn_b, ln_g, ln_b, out, N);
}

// round 4
// speedup vs baseline: 2.8430x; 2.8430x over previous
#include <cuda_runtime.h>
#include <cuda_bf16.h>

#define NMAX 50000
#define EMAX 800000
#define C 128
#define TOTK 20
#define NMAT 50

// ---------------- scratch (static device globals; no allocation) ----------------
__device__ int   g_degsrc[NMAX];
__device__ int   g_degdst[NMAX];
__device__ int   g_cursor[NMAX];
__device__ float g_dinv[NMAX];
__device__ int   g_rowptr[NMAX + 1];
__device__ int   g_bsum[64];
__device__ int   g_is64;
__device__ int   g_nsrc[EMAX];
__device__ float g_nw[EMAX];
__device__ __align__(16) float g_T0[NMAX * C];
__device__ __align__(16) float g_T1[NMAX * C];
__device__ __align__(16) float g_T2[NMAX * C];
__device__ __align__(16) float g_Y[(size_t)NMAX * 512];
// split-bf16 Chebyshev bases: [k][node][c]
__device__ __align__(16) unsigned short g_Th[(size_t)TOTK * NMAX * C];
__device__ __align__(16) unsigned short g_Tl[(size_t)TOTK * NMAX * C];
// split-bf16 transposed weights: [mat][n][k]
__device__ __align__(16) unsigned short g_Wh[(size_t)NMAT * C * C];
__device__ __align__(16) unsigned short g_Wl[(size_t)NMAT * C * C];

__device__ __forceinline__ const float* sel_buf(int id, const float* x) {
    switch (id) { case 0: return g_T0; case 1: return g_T1; case 2: return g_T2; default: return x; }
}
__device__ __forceinline__ float* sel_buf_w(int id) {
    switch (id) { case 0: return g_T0; case 1: return g_T1; default: return g_T2; }
}

__device__ __forceinline__ long long load_idx(const void* ei, int is64, size_t pos) {
    if (is64) return ((const long long*)ei)[pos];
    return (long long)((const int*)ei)[pos];
}

__device__ __forceinline__ void split_store(float v, size_t o) {
    __nv_bfloat16 h = __float2bfloat16(v);
    g_Th[o] = __bfloat16_as_ushort(h);
    g_Tl[o] = __bfloat16_as_ushort(__float2bfloat16(v - __bfloat162float(h)));
}

// ---------------- dtype detection ----------------
__global__ void k_detect(const void* ei, int E, int N) {
    __shared__ int bad;
    if (threadIdx.x == 0) bad = 0;
    __syncthreads();
    int cnt = min(E, 2048);
    for (int i = threadIdx.x; i < cnt; i += blockDim.x) {
        long long v = ((const long long*)ei)[i];
        if (v < 0 || v >= (long long)N) atomicOr(&bad, 1);
    }
    __syncthreads();
    if (threadIdx.x == 0) g_is64 = bad ? 0 : 1;
}

// ---------------- setup kernels ----------------
__global__ void k_zero(int N) {
    int i = blockIdx.x * blockDim.x + threadIdx.x;
    if (i < N) { g_degsrc[i] = 0; g_degdst[i] = 0; g_cursor[i] = 0; }
}

__global__ void k_deg(const void* __restrict__ ei, int E, int N) {
    int e = blockIdx.x * blockDim.x + threadIdx.x;
    if (e < E) {
        int is64 = g_is64;
        long long s = load_idx(ei, is64, e);
        long long d = load_idx(ei, is64, (size_t)E + e);
        if (s >= 0 && s < N) atomicAdd(&g_degsrc[(int)s], 1);
        if (d >= 0 && d < N) atomicAdd(&g_degdst[(int)d], 1);
    }
}

__global__ void k_dinv(int N) {
    int i = blockIdx.x * blockDim.x + threadIdx.x;
    if (i < N) {
        int d = g_degsrc[i];
        g_dinv[i] = (d > 0) ? rsqrtf((float)d) : 0.0f;
    }
}

__global__ void k_scan1(int N) {
    __shared__ int sh[1024];
    int tid = threadIdx.x;
    int i = blockIdx.x * 1024 + tid;
    int v = (i < N) ? g_degdst[i] : 0;
    sh[tid] = v;
    __syncthreads();
    for (int off = 1; off < 1024; off <<= 1) {
        int t = (tid >= off) ? sh[tid - off] : 0;
        __syncthreads();
        sh[tid] += t;
        __syncthreads();
    }
    if (i < N) g_rowptr[i] = sh[tid] - v;
    if (tid == 1023) g_bsum[blockIdx.x] = sh[1023];
}

__global__ void k_scan2(int nb, int N) {
    if (threadIdx.x == 0 && blockIdx.x == 0) {
        int run = 0;
        for (int b = 0; b < nb; b++) { int v = g_bsum[b]; g_bsum[b] = run; run += v; }
        g_rowptr[N] = run;
    }
}

__global__ void k_scan3(int N) {
    int i = blockIdx.x * 1024 + threadIdx.x;
    if (i < N) g_rowptr[i] += g_bsum[blockIdx.x];
}

__global__ void k_scatter(const void* __restrict__ ei, int E, int N) {
    int e = blockIdx.x * blockDim.x + threadIdx.x;
    if (e < E) {
        int is64 = g_is64;
        long long sl = load_idx(ei, is64, e);
        long long dl = load_idx(ei, is64, (size_t)E + e);
        if (sl < 0 || sl >= N || dl < 0 || dl >= N) return;
        int s = (int)sl, d = (int)dl;
        float w = -g_dinv[s] * g_dinv[d] - 1.0f;
        int pos = g_rowptr[d] + atomicAdd(&g_cursor[d], 1);
        g_nsrc[pos] = s;
        g_nw[pos]   = w;
    }
}

// ---------------- weight prep: transpose + split into bf16 hi/lo ----------------
__global__ void k_wprep(const float* __restrict__ cheb_w) {
    int mat = blockIdx.x;
    const float* W = cheb_w + (size_t)mat * C * C;
    for (int idx = threadIdx.x; idx < C * C; idx += blockDim.x) {
        int kk = idx >> 7, n = idx & 127;
        float v = W[idx];
        __nv_bfloat16 h = __float2bfloat16(v);
        size_t o = (size_t)mat * C * C + (size_t)n * C + kk;
        g_Wh[o] = __bfloat16_as_ushort(h);
        g_Wl[o] = __bfloat16_as_ushort(__float2bfloat16(v - __bfloat162float(h)));
    }
}

// ---------------- x -> T_0 split ----------------
__global__ void k_xconv(const float* __restrict__ x, int N) {
    size_t i = (size_t)blockIdx.x * blockDim.x + threadIdx.x;
    if (i < (size_t)N * C) split_store(x[i], i);
}

// ---------------- propagation (+ split-bf16 emission of T_kv) ----------------
__global__ void k_prop(int in_id, int sub_id, int out_id, const float* __restrict__ x,
                       float alpha, float beta, int N, int kv) {
    const float* Tin  = sel_buf(in_id, x);
    const float* Tsub = sel_buf(sub_id, x);
    float*       Tout = sel_buf_w(out_id);

    int n = blockIdx.x;
    int c = threadIdx.x;
    int beg = g_rowptr[n], end = g_rowptr[n + 1];
    __shared__ int   ss[64];
    __shared__ float sw[64];
    float acc = 0.0f;
    for (int t0 = beg; t0 < end; t0 += 64) {
        int cnt = min(64, end - t0);
        if (c < cnt) { ss[c] = g_nsrc[t0 + c]; sw[c] = g_nw[t0 + c]; }
        __syncthreads();
        int j = 0;
        for (; j + 4 <= cnt; j += 4) {
            float a0 = Tin[(size_t)ss[j]     * C + c];
            float a1 = Tin[(size_t)ss[j + 1] * C + c];
            float a2 = Tin[(size_t)ss[j + 2] * C + c];
            float a3 = Tin[(size_t)ss[j + 3] * C + c];
            acc += sw[j] * a0; acc += sw[j + 1] * a1;
            acc += sw[j + 2] * a2; acc += sw[j + 3] * a3;
        }
        for (; j < cnt; ++j) acc += sw[j] * Tin[(size_t)ss[j] * C + c];
        __syncthreads();
    }
    float v = alpha * acc + beta * Tsub[(size_t)n * C + c];
    Tout[(size_t)n * C + c] = v;
    split_store(v, (size_t)kv * N * C + (size_t)n * C + c);
}

// ---------------- fused tensor-core GEMM ----------------
// block = (filter f = blockIdx.x, row tile = blockIdx.y). Y tile accumulated in regs
// over all K_f bases via mma.sync bf16 3-product split; written once with bias.
#define SW 36            // padded smem row stride (words); 64 bf16 = 32 words + 4 pad
#define BUFW (4 * 128 * SW)   // words per pipeline buffer (Ah, Al, Wh, Wl)

__device__ __forceinline__ void mma_bf16(float* c, const unsigned* a, const unsigned* b) {
    asm volatile(
        "mma.sync.aligned.m16n8k16.row.col.f32.bf16.bf16.f32 "
        "{%0,%1,%2,%3}, {%4,%5,%6,%7}, {%8,%9}, {%0,%1,%2,%3};\n"
        : "+f"(c[0]), "+f"(c[1]), "+f"(c[2]), "+f"(c[3])
        : "r"(a[0]), "r"(a[1]), "r"(a[2]), "r"(a[3]), "r"(b[0]), "r"(b[1]));
}

__device__ __forceinline__ void cpa16(unsigned saddr, const void* g, int sz) {
    asm volatile("cp.async.cg.shared.global [%0], [%1], 16, %2;\n"
                 :: "r"(saddr), "l"(g), "r"(sz));
}

__device__ __forceinline__ void gemm_load_chunk(unsigned sbase, int buf, int kv, int mat,
                                                int ch, int tilebase, int N) {
    int t = threadIdx.x;
    const unsigned short* Ah = g_Th + (size_t)kv * N * C;
    const unsigned short* Al = g_Tl + (size_t)kv * N * C;
    const unsigned short* Wh = g_Wh + (size_t)mat * C * C;
    const unsigned short* Wl = g_Wl + (size_t)mat * C * C;
    unsigned b0 = sbase + (unsigned)(buf * BUFW) * 4;
#pragma unroll
    for (int j = 0; j < 4; ++j) {
        int idx = t + j * 256;
        int row = idx >> 3, seg = idx & 7;
        unsigned sm_off = (unsigned)(row * SW + seg * 4) * 4;
        int grow = tilebase + row;
        int ok = (grow < N) ? 16 : 0;
        int growc = (grow < N) ? grow : (N - 1);
        size_t ga = (size_t)growc * C + ch * 64 + seg * 8;
        cpa16(b0 + sm_off,                     Ah + ga, ok);
        cpa16(b0 + (unsigned)(128*SW)*4  + sm_off, Al + ga, ok);
        size_t gw = (size_t)row * C + ch * 64 + seg * 8;
        cpa16(b0 + (unsigned)(2*128*SW)*4 + sm_off, Wh + gw, 16);
        cpa16(b0 + (unsigned)(3*128*SW)*4 + sm_off, Wl + gw, 16);
    }
}

extern __shared__ __align__(16) unsigned sm_u[];

__global__ void __launch_bounds__(256)
k_gemm_all(const float* __restrict__ cheb_b, int N) {
    int f = blockIdx.x;
    int tilebase = blockIdx.y * 128;
    int Kf = 5 * (f + 1);
    int off = 5 * f * (f + 1) / 2;
    int NC = Kf * 2;

    unsigned sbase = (unsigned)__cvta_generic_to_shared(sm_u);
    int t = threadIdx.x;
    int lane = t & 31, w = t >> 5;
    int warp_m = w & 3, warp_n = w >> 2;   // 4 x 2 warps; warp tile 32m x 64n
    int g = lane >> 2, tig = lane & 3;

    float acc[2][8][4];
#pragma unroll
    for (int mt = 0; mt < 2; ++mt)
#pragma unroll
        for (int nt = 0; nt < 8; ++nt)
#pragma unroll
            for (int r = 0; r < 4; ++r) acc[mt][nt][r] = 0.0f;

    // prefetch chunk 0
    gemm_load_chunk(sbase, 0, 0, off, 0, tilebase, N);
    asm volatile("cp.async.commit_group;\n" ::: "memory");

    for (int i = 0; i < NC; ++i) {
        if (i + 1 < NC) {
            int kv = (i + 1) >> 1, ch = (i + 1) & 1;
            gemm_load_chunk(sbase, (i + 1) & 1, kv, off + kv, ch, tilebase, N);
        }
        asm volatile("cp.async.commit_group;\n" ::: "memory");
        if (i + 1 < NC) asm volatile("cp.async.wait_group 1;\n" ::: "memory");
        else            asm volatile("cp.async.wait_group 0;\n" ::: "memory");
        __syncthreads();

        const unsigned* Ah_s = sm_u + (i & 1) * BUFW;
        const unsigned* Al_s = Ah_s + 128 * SW;
        const unsigned* Wh_s = Ah_s + 2 * 128 * SW;
        const unsigned* Wl_s = Ah_s + 3 * 128 * SW;

#pragma unroll
        for (int s = 0; s < 4; ++s) {
            unsigned ah[2][4], al[2][4], bh[8][2], bl[8][2];
#pragma unroll
            for (int mt = 0; mt < 2; ++mt) {
                int w0 = (warp_m * 32 + mt * 16 + g) * SW + s * 8 + tig;
                ah[mt][0] = Ah_s[w0];           ah[mt][1] = Ah_s[w0 + 8 * SW];
                ah[mt][2] = Ah_s[w0 + 4];       ah[mt][3] = Ah_s[w0 + 8 * SW + 4];
                al[mt][0] = Al_s[w0];           al[mt][1] = Al_s[w0 + 8 * SW];
                al[mt][2] = Al_s[w0 + 4];       al[mt][3] = Al_s[w0 + 8 * SW + 4];
            }
#pragma unroll
            for (int nt = 0; nt < 8; ++nt) {
                int w0 = (warp_n * 64 + nt * 8 + g) * SW + s * 8 + tig;
                bh[nt][0] = Wh_s[w0];  bh[nt][1] = Wh_s[w0 + 4];
                bl[nt][0] = Wl_s[w0];  bl[nt][1] = Wl_s[w0 + 4];
            }
#pragma unroll
            for (int mt = 0; mt < 2; ++mt)
#pragma unroll
                for (int nt = 0; nt < 8; ++nt) {
                    mma_bf16(acc[mt][nt], ah[mt], bh[nt]);
                    mma_bf16(acc[mt][nt], ah[mt], bl[nt]);
                    mma_bf16(acc[mt][nt], al[mt], bh[nt]);
                }
        }
        __syncthreads();
    }

    // epilogue: add bias, write Y once
#pragma unroll
    for (int mt = 0; mt < 2; ++mt) {
        int r0 = tilebase + warp_m * 32 + mt * 16 + g;
#pragma unroll
        for (int nt = 0; nt < 8; ++nt) {
            int col = warp_n * 64 + nt * 8 + tig * 2;
            float b0v = cheb_b[f * 128 + col];
            float b1v = cheb_b[f * 128 + col + 1];
            size_t gc = (size_t)f * 128 + col;
            if (r0 < N) {
                float2 v = make_float2(acc[mt][nt][0] + b0v, acc[mt][nt][1] + b1v);
                *(float2*)&g_Y[(size_t)r0 * 512 + gc] = v;
            }
            if (r0 + 8 < N) {
                float2 v = make_float2(acc[mt][nt][2] + b0v, acc[mt][nt][3] + b1v);
                *(float2*)&g_Y[(size_t)(r0 + 8) * 512 + gc] = v;
            }
        }
    }
}

// ---------------- attention softmax + combine + layernorm ----------------
__global__ void k_final(const float* __restrict__ attn_w, const float* __restrict__ attn_b,
                        const float* __restrict__ ln_g, const float* __restrict__ ln_b,
                        float* __restrict__ out, int N) {
    int n = blockIdx.x, t = threadIdx.x;
    const float* yr = g_Y + (size_t)n * 512;

    float l[4] = {0.f, 0.f, 0.f, 0.f};
    for (int j = t; j < 512; j += 128) {
        float v = yr[j];
        float4 aw = *(const float4*)&attn_w[j * 4];
        l[0] += v * aw.x; l[1] += v * aw.y; l[2] += v * aw.z; l[3] += v * aw.w;
    }
#pragma unroll
    for (int o = 16; o > 0; o >>= 1) {
        l[0] += __shfl_down_sync(0xffffffffu, l[0], o);
        l[1] += __shfl_down_sync(0xffffffffu, l[1], o);
        l[2] += __shfl_down_sync(0xffffffffu, l[2], o);
        l[3] += __shfl_down_sync(0xffffffffu, l[3], o);
    }
    __shared__ float sr[4][4];
    __shared__ float sa[4];
    __shared__ float rs[4];
    int lane = t & 31, w = t >> 5;
    if (lane == 0) { sr[w][0] = l[0]; sr[w][1] = l[1]; sr[w][2] = l[2]; sr[w][3] = l[3]; }
    __syncthreads();
    if (t == 0) {
        float L[4];
#pragma unroll
        for (int i = 0; i < 4; ++i)
            L[i] = sr[0][i] + sr[1][i] + sr[2][i] + sr[3][i] + attn_b[i];
        float m = fmaxf(fmaxf(L[0], L[1]), fmaxf(L[2], L[3]));
        float e0 = expf(L[0] - m), e1 = expf(L[1] - m), e2 = expf(L[2] - m), e3 = expf(L[3] - m);
        float s = e0 + e1 + e2 + e3;
        sa[0] = e0 / s; sa[1] = e1 / s; sa[2] = e2 / s; sa[3] = e3 / s;
    }
    __syncthreads();

    float cmb = sa[0] * yr[t] + sa[1] * yr[128 + t] + sa[2] * yr[256 + t] + sa[3] * yr[384 + t];

    float v = cmb;
#pragma unroll
    for (int o = 16; o > 0; o >>= 1) v += __shfl_down_sync(0xffffffffu, v, o);
    if (lane == 0) rs[w] = v;
    __syncthreads();
    float mu = (rs[0] + rs[1] + rs[2] + rs[3]) * (1.0f / 128.0f);
    __syncthreads();

    float d = cmb - mu;
    float v2 = d * d;
#pragma unroll
    for (int o = 16; o > 0; o >>= 1) v2 += __shfl_down_sync(0xffffffffu, v2, o);
    if (lane == 0) rs[w] = v2;
    __syncthreads();
    float var = (rs[0] + rs[1] + rs[2] + rs[3]) * (1.0f / 128.0f);
    float inv = rsqrtf(var + 1e-5f);

    out[(size_t)n * 128 + t] = d * inv * ln_g[t] + ln_b[t];
}

// ---------------- host ----------------
extern "C" void kernel_launch(void* const* d_in, const int* in_sizes, int n_in,
                              void* d_out, int out_size) {
    const float* x      = (const float*)d_in[0];
    const void*  ei     = d_in[1];
    const float* cheb_w = (const float*)d_in[2];
    const float* cheb_b = (const float*)d_in[3];
    const float* attn_w = (const float*)d_in[4];
    const float* attn_b = (const float*)d_in[5];
    const float* ln_g   = (const float*)d_in[6];
    const float* ln_b   = (const float*)d_in[7];
    float*       out    = (float*)d_out;

    int N = in_sizes[0] / 128;
    int E = in_sizes[1] / 2;
    if (N > NMAX) N = NMAX;
    if (E > EMAX) E = EMAX;

    static int smem_set = 0;
    if (!smem_set) {
        cudaFuncSetAttribute(k_gemm_all, cudaFuncAttributeMaxDynamicSharedMemorySize,
                             2 * BUFW * 4);
        smem_set = 1;
    }

    // graph structure build
    k_detect<<<1, 256>>>(ei, E, N);
    k_zero<<<(N + 255) / 256, 256>>>(N);
    k_deg<<<(E + 255) / 256, 256>>>(ei, E, N);
    k_dinv<<<(N + 255) / 256, 256>>>(N);
    int nb = (N + 1023) / 1024;
    k_scan1<<<nb, 1024>>>(N);
    k_scan2<<<1, 32>>>(nb, N);
    k_scan3<<<nb, 1024>>>(N);
    k_scatter<<<(E + 255) / 256, 256>>>(ei, E, N);

    // weight prep + T0 split (independent of graph build; overlap fine)
    k_wprep<<<NMAT, 256>>>(cheb_w);
    {
        size_t tot = (size_t)N * C;
        k_xconv<<<(unsigned)((tot + 255) / 256), 256>>>(x, N);
    }

    // buffer id schedule: id 3 = x; ids 0..2 = g_T0..g_T2 (ring)
    int id[20];
    id[0] = 3;
    for (int k = 1; k < 20; ++k) id[k] = (k - 1) % 3;

    // Chebyshev recursion, emitting split-bf16 T_k
    k_prop<<<N, 128>>>(id[0], id[0], id[1], x, 1.0f, 0.0f, N, 1);
    for (int k = 2; k < 20; ++k)
        k_prop<<<N, 128>>>(id[k - 1], id[k - 2], id[k], x, 2.0f, -1.0f, N, k);

    // fused tensor-core GEMM: all filters, all k, Y written once
    dim3 gg(4, (N + 127) / 128);
    k_gemm_all<<<gg, 256, 2 * BUFW * 4>>>(cheb_b, N);

    k_final<<<N, 128>>>(attn_w, attn_b, ln_g, ln_b, out, N);
}

// round 7
// speedup vs baseline: 3.7375x; 1.3147x over previous
#include <cuda_runtime.h>
#include <cuda_bf16.h>

#define NMAX 50000
#define EMAX 800000
#define C 128
#define TOTK 20
#define NMAT 50

// ---------------- scratch (static device globals; no allocation) ----------------
__device__ int   g_degsrc[NMAX];
__device__ int   g_degdst[NMAX];
__device__ int   g_cursor[NMAX];
__device__ float g_dinv[NMAX];
__device__ int   g_rowptr[NMAX + 1];
__device__ int   g_bsum[64];
__device__ int   g_is64;
__device__ __align__(8) int2 g_epack[EMAX];      // (src, w-as-int) packed per edge
__device__ __align__(16) float g_T0[NMAX * C];
__device__ __align__(16) float g_T1[NMAX * C];
__device__ __align__(16) float g_T2[NMAX * C];
__device__ __align__(16) float g_Y[(size_t)NMAX * 512];
// split-bf16 Chebyshev bases: [k][node][c]
__device__ __align__(16) unsigned short g_Th[(size_t)TOTK * NMAX * C];
__device__ __align__(16) unsigned short g_Tl[(size_t)TOTK * NMAX * C];
// split-bf16 transposed weights: [mat][n][k]
__device__ __align__(16) unsigned short g_Wh[(size_t)NMAT * C * C];
__device__ __align__(16) unsigned short g_Wl[(size_t)NMAT * C * C];

__device__ __forceinline__ const float* sel_buf(int id, const float* x) {
    switch (id) { case 0: return g_T0; case 1: return g_T1; case 2: return g_T2; default: return x; }
}
__device__ __forceinline__ float* sel_buf_w(int id) {
    switch (id) { case 0: return g_T0; case 1: return g_T1; default: return g_T2; }
}

__device__ __forceinline__ long long load_idx(const void* ei, int is64, size_t pos) {
    if (is64) return ((const long long*)ei)[pos];
    return (long long)((const int*)ei)[pos];
}

// ---------------- dtype detection ----------------
__global__ void k_detect(const void* ei, int E, int N) {
    __shared__ int bad;
    if (threadIdx.x == 0) bad = 0;
    __syncthreads();
    int cnt = min(E, 2048);
    for (int i = threadIdx.x; i < cnt; i += blockDim.x) {
        long long v = ((const long long*)ei)[i];
        if (v < 0 || v >= (long long)N) atomicOr(&bad, 1);
    }
    __syncthreads();
    if (threadIdx.x == 0) g_is64 = bad ? 0 : 1;
}

// ---------------- setup kernels ----------------
__global__ void k_zero(int N) {
    int i = blockIdx.x * blockDim.x + threadIdx.x;
    if (i < N) { g_degsrc[i] = 0; g_degdst[i] = 0; g_cursor[i] = 0; }
}

__global__ void k_deg(const void* __restrict__ ei, int E, int N) {
    int e = blockIdx.x * blockDim.x + threadIdx.x;
    if (e < E) {
        int is64 = g_is64;
        long long s = load_idx(ei, is64, e);
        long long d = load_idx(ei, is64, (size_t)E + e);
        if (s >= 0 && s < N) atomicAdd(&g_degsrc[(int)s], 1);
        if (d >= 0 && d < N) atomicAdd(&g_degdst[(int)d], 1);
    }
}

__global__ void k_dinv(int N) {
    int i = blockIdx.x * blockDim.x + threadIdx.x;
    if (i < N) {
        int d = g_degsrc[i];
        g_dinv[i] = (d > 0) ? rsqrtf((float)d) : 0.0f;
    }
}

__global__ void k_scan1(int N) {
    __shared__ int sh[1024];
    int tid = threadIdx.x;
    int i = blockIdx.x * 1024 + tid;
    int v = (i < N) ? g_degdst[i] : 0;
    sh[tid] = v;
    __syncthreads();
    for (int off = 1; off < 1024; off <<= 1) {
        int t = (tid >= off) ? sh[tid - off] : 0;
        __syncthreads();
        sh[tid] += t;
        __syncthreads();
    }
    if (i < N) g_rowptr[i] = sh[tid] - v;
    if (tid == 1023) g_bsum[blockIdx.x] = sh[1023];
}

__global__ void k_scan2(int nb, int N) {
    if (threadIdx.x == 0 && blockIdx.x == 0) {
        int run = 0;
        for (int b = 0; b < nb; b++) { int v = g_bsum[b]; g_bsum[b] = run; run += v; }
        g_rowptr[N] = run;
    }
}

__global__ void k_scan3(int N) {
    int i = blockIdx.x * 1024 + threadIdx.x;
    if (i < N) g_rowptr[i] += g_bsum[blockIdx.x];
}

__global__ void k_scatter(const void* __restrict__ ei, int E, int N) {
    int e = blockIdx.x * blockDim.x + threadIdx.x;
    if (e < E) {
        int is64 = g_is64;
        long long sl = load_idx(ei, is64, e);
        long long dl = load_idx(ei, is64, (size_t)E + e);
        if (sl < 0 || sl >= N || dl < 0 || dl >= N) return;
        int s = (int)sl, d = (int)dl;
        float w = -g_dinv[s] * g_dinv[d] - 1.0f;
        int pos = g_rowptr[d] + atomicAdd(&g_cursor[d], 1);
        g_epack[pos] = make_int2(s, __float_as_int(w));
    }
}

// ---------------- weight prep: transpose + split into bf16 hi/lo ----------------
__global__ void k_wprep(const float* __restrict__ cheb_w) {
    int mat = blockIdx.x;
    const float* W = cheb_w + (size_t)mat * C * C;
    for (int idx = threadIdx.x; idx < C * C; idx += blockDim.x) {
        int kk = idx >> 7, n = idx & 127;
        float v = W[idx];
        __nv_bfloat16 h = __float2bfloat16(v);
        size_t o = (size_t)mat * C * C + (size_t)n * C + kk;
        g_Wh[o] = __bfloat16_as_ushort(h);
        g_Wl[o] = __bfloat16_as_ushort(__float2bfloat16(v - __bfloat162float(h)));
    }
}

// ---------------- x -> T_0 split ----------------
__global__ void k_xconv(const float* __restrict__ x, int N) {
    size_t i = (size_t)blockIdx.x * blockDim.x + threadIdx.x;
    if (i < (size_t)N * C) {
        float v = x[i];
        __nv_bfloat16 h = __float2bfloat16(v);
        g_Th[i] = __bfloat16_as_ushort(h);
        g_Tl[i] = __bfloat16_as_ushort(__float2bfloat16(v - __bfloat162float(h)));
    }
}

// ---------------- propagation v2: warp-per-node, float4, packed edges ------------
// Tout = alpha * (L' @ Tin) + beta * Tsub; also emits split-bf16 T_kv.
__global__ void __launch_bounds__(256)
k_prop(int in_id, int sub_id, int out_id, const float* __restrict__ xp,
       float alpha, float beta, int N, int kv) {
    const float4* Tin  = (const float4*)sel_buf(in_id, xp);
    const float4* Tsub = (const float4*)sel_buf(sub_id, xp);
    float4*       Tout = (float4*)sel_buf_w(out_id);

    int node = (blockIdx.x * blockDim.x + threadIdx.x) >> 5;
    if (node >= N) return;
    int lane = threadIdx.x & 31;

    int beg = g_rowptr[node], end = g_rowptr[node + 1];
    float4 acc = make_float4(0.f, 0.f, 0.f, 0.f);

    int j = beg;
    for (; j + 4 <= end; j += 4) {
        int2 e0 = g_epack[j];
        int2 e1 = g_epack[j + 1];
        int2 e2 = g_epack[j + 2];
        int2 e3 = g_epack[j + 3];
        float4 a0 = Tin[(size_t)e0.x * 32 + lane];
        float4 a1 = Tin[(size_t)e1.x * 32 + lane];
        float4 a2 = Tin[(size_t)e2.x * 32 + lane];
        float4 a3 = Tin[(size_t)e3.x * 32 + lane];
        float w0 = __int_as_float(e0.y), w1 = __int_as_float(e1.y);
        float w2 = __int_as_float(e2.y), w3 = __int_as_float(e3.y);
        acc.x += w0 * a0.x; acc.y += w0 * a0.y; acc.z += w0 * a0.z; acc.w += w0 * a0.w;
        acc.x += w1 * a1.x; acc.y += w1 * a1.y; acc.z += w1 * a1.z; acc.w += w1 * a1.w;
        acc.x += w2 * a2.x; acc.y += w2 * a2.y; acc.z += w2 * a2.z; acc.w += w2 * a2.w;
        acc.x += w3 * a3.x; acc.y += w3 * a3.y; acc.z += w3 * a3.z; acc.w += w3 * a3.w;
    }
    for (; j < end; ++j) {
        int2 e = g_epack[j];
        float w = __int_as_float(e.y);
        float4 a = Tin[(size_t)e.x * 32 + lane];
        acc.x += w * a.x; acc.y += w * a.y; acc.z += w * a.z; acc.w += w * a.w;
    }

    float4 sv = Tsub[(size_t)node * 32 + lane];
    float4 v;
    v.x = alpha * acc.x + beta * sv.x;
    v.y = alpha * acc.y + beta * sv.y;
    v.z = alpha * acc.z + beta * sv.z;
    v.w = alpha * acc.w + beta * sv.w;
    Tout[(size_t)node * 32 + lane] = v;

    // fused split-bf16 emission (8B stores)
    __nv_bfloat16 hx = __float2bfloat16(v.x), hy = __float2bfloat16(v.y);
    __nv_bfloat16 hz = __float2bfloat16(v.z), hw = __float2bfloat16(v.w);
    ushort4 hi = make_ushort4(__bfloat16_as_ushort(hx), __bfloat16_as_ushort(hy),
                              __bfloat16_as_ushort(hz), __bfloat16_as_ushort(hw));
    ushort4 lo = make_ushort4(
        __bfloat16_as_ushort(__float2bfloat16(v.x - __bfloat162float(hx))),
        __bfloat16_as_ushort(__float2bfloat16(v.y - __bfloat162float(hy))),
        __bfloat16_as_ushort(__float2bfloat16(v.z - __bfloat162float(hz))),
        __bfloat16_as_ushort(__float2bfloat16(v.w - __bfloat162float(hw))));
    size_t o = ((size_t)kv * N + node) * C + lane * 4;
    *(ushort4*)&g_Th[o] = hi;
    *(ushort4*)&g_Tl[o] = lo;
}

// ---------------- fused tensor-core GEMM ----------------
#define SW 36
#define BUFW (4 * 128 * SW)

__device__ __forceinline__ void mma_bf16(float* c, const unsigned* a, const unsigned* b) {
    asm volatile(
        "mma.sync.aligned.m16n8k16.row.col.f32.bf16.bf16.f32 "
        "{%0,%1,%2,%3}, {%4,%5,%6,%7}, {%8,%9}, {%0,%1,%2,%3};\n"
        : "+f"(c[0]), "+f"(c[1]), "+f"(c[2]), "+f"(c[3])
        : "r"(a[0]), "r"(a[1]), "r"(a[2]), "r"(a[3]), "r"(b[0]), "r"(b[1]));
}

__device__ __forceinline__ void cpa16(unsigned saddr, const void* g, int sz) {
    asm volatile("cp.async.cg.shared.global [%0], [%1], 16, %2;\n"
                 :: "r"(saddr), "l"(g), "r"(sz));
}

__device__ __forceinline__ void gemm_load_chunk(unsigned sbase, int buf, int kv, int mat,
                                                int ch, int tilebase, int N) {
    int t = threadIdx.x;
    const unsigned short* Ah = g_Th + (size_t)kv * N * C;
    const unsigned short* Al = g_Tl + (size_t)kv * N * C;
    const unsigned short* Wh = g_Wh + (size_t)mat * C * C;
    const unsigned short* Wl = g_Wl + (size_t)mat * C * C;
    unsigned b0 = sbase + (unsigned)(buf * BUFW) * 4;
#pragma unroll
    for (int j = 0; j < 4; ++j) {
        int idx = t + j * 256;
        int row = idx >> 3, seg = idx & 7;
        unsigned sm_off = (unsigned)(row * SW + seg * 4) * 4;
        int grow = tilebase + row;
        int ok = (grow < N) ? 16 : 0;
        int growc = (grow < N) ? grow : (N - 1);
        size_t ga = (size_t)growc * C + ch * 64 + seg * 8;
        cpa16(b0 + sm_off,                         Ah + ga, ok);
        cpa16(b0 + (unsigned)(128*SW)*4  + sm_off, Al + ga, ok);
        size_t gw = (size_t)row * C + ch * 64 + seg * 8;
        cpa16(b0 + (unsigned)(2*128*SW)*4 + sm_off, Wh + gw, 16);
        cpa16(b0 + (unsigned)(3*128*SW)*4 + sm_off, Wl + gw, 16);
    }
}

extern __shared__ __align__(16) unsigned sm_u[];

__global__ void __launch_bounds__(256)
k_gemm_all(const float* __restrict__ cheb_b, int N) {
    int f = blockIdx.x;
    int tilebase = blockIdx.y * 128;
    int Kf = 5 * (f + 1);
    int off = 5 * f * (f + 1) / 2;
    int NC = Kf * 2;

    unsigned sbase = (unsigned)__cvta_generic_to_shared(sm_u);
    int t = threadIdx.x;
    int lane = t & 31, w = t >> 5;
    int warp_m = w & 3, warp_n = w >> 2;
    int g = lane >> 2, tig = lane & 3;

    float acc[2][8][4];
#pragma unroll
    for (int mt = 0; mt < 2; ++mt)
#pragma unroll
        for (int nt = 0; nt < 8; ++nt)
#pragma unroll
            for (int r = 0; r < 4; ++r) acc[mt][nt][r] = 0.0f;

    gemm_load_chunk(sbase, 0, 0, off, 0, tilebase, N);
    asm volatile("cp.async.commit_group;\n" ::: "memory");

    for (int i = 0; i < NC; ++i) {
        if (i + 1 < NC) {
            int kv = (i + 1) >> 1, ch = (i + 1) & 1;
            gemm_load_chunk(sbase, (i + 1) & 1, kv, off + kv, ch, tilebase, N);
        }
        asm volatile("cp.async.commit_group;\n" ::: "memory");
        if (i + 1 < NC) asm volatile("cp.async.wait_group 1;\n" ::: "memory");
        else            asm volatile("cp.async.wait_group 0;\n" ::: "memory");
        __syncthreads();

        const unsigned* Ah_s = sm_u + (i & 1) * BUFW;
        const unsigned* Al_s = Ah_s + 128 * SW;
        const unsigned* Wh_s = Ah_s + 2 * 128 * SW;
        const unsigned* Wl_s = Ah_s + 3 * 128 * SW;

#pragma unroll
        for (int s = 0; s < 4; ++s) {
            unsigned ah[2][4], al[2][4], bh[8][2], bl[8][2];
#pragma unroll
            for (int mt = 0; mt < 2; ++mt) {
                int w0 = (warp_m * 32 + mt * 16 + g) * SW + s * 8 + tig;
                ah[mt][0] = Ah_s[w0];           ah[mt][1] = Ah_s[w0 + 8 * SW];
                ah[mt][2] = Ah_s[w0 + 4];       ah[mt][3] = Ah_s[w0 + 8 * SW + 4];
                al[mt][0] = Al_s[w0];           al[mt][1] = Al_s[w0 + 8 * SW];
                al[mt][2] = Al_s[w0 + 4];       al[mt][3] = Al_s[w0 + 8 * SW + 4];
            }
#pragma unroll
            for (int nt = 0; nt < 8; ++nt) {
                int w0 = (warp_n * 64 + nt * 8 + g) * SW + s * 8 + tig;
                bh[nt][0] = Wh_s[w0];  bh[nt][1] = Wh_s[w0 + 4];
                bl[nt][0] = Wl_s[w0];  bl[nt][1] = Wl_s[w0 + 4];
            }
#pragma unroll
            for (int mt = 0; mt < 2; ++mt)
#pragma unroll
                for (int nt = 0; nt < 8; ++nt) {
                    mma_bf16(acc[mt][nt], ah[mt], bh[nt]);
                    mma_bf16(acc[mt][nt], ah[mt], bl[nt]);
                    mma_bf16(acc[mt][nt], al[mt], bh[nt]);
                }
        }
        __syncthreads();
    }

#pragma unroll
    for (int mt = 0; mt < 2; ++mt) {
        int r0 = tilebase + warp_m * 32 + mt * 16 + g;
#pragma unroll
        for (int nt = 0; nt < 8; ++nt) {
            int col = warp_n * 64 + nt * 8 + tig * 2;
            float b0v = cheb_b[f * 128 + col];
            float b1v = cheb_b[f * 128 + col + 1];
            size_t gc = (size_t)f * 128 + col;
            if (r0 < N) {
                float2 v = make_float2(acc[mt][nt][0] + b0v, acc[mt][nt][1] + b1v);
                *(float2*)&g_Y[(size_t)r0 * 512 + gc] = v;
            }
            if (r0 + 8 < N) {
                float2 v = make_float2(acc[mt][nt][2] + b0v, acc[mt][nt][3] + b1v);
                *(float2*)&g_Y[(size_t)(r0 + 8) * 512 + gc] = v;
            }
        }
    }
}

// ---------------- attention softmax + combine + layernorm ----------------
__global__ void k_final(const float* __restrict__ attn_w, const float* __restrict__ attn_b,
                        const float* __restrict__ ln_g, const float* __restrict__ ln_b,
                        float* __restrict__ out, int N) {
    int n = blockIdx.x, t = threadIdx.x;
    const float* yr = g_Y + (size_t)n * 512;

    float l[4] = {0.f, 0.f, 0.f, 0.f};
    for (int j = t; j < 512; j += 128) {
        float v = yr[j];
        float4 aw = *(const float4*)&attn_w[j * 4];
        l[0] += v * aw.x; l[1] += v * aw.y; l[2] += v * aw.z; l[3] += v * aw.w;
    }
#pragma unroll
    for (int o = 16; o > 0; o >>= 1) {
        l[0] += __shfl_down_sync(0xffffffffu, l[0], o);
        l[1] += __shfl_down_sync(0xffffffffu, l[1], o);
        l[2] += __shfl_down_sync(0xffffffffu, l[2], o);
        l[3] += __shfl_down_sync(0xffffffffu, l[3], o);
    }
    __shared__ float sr[4][4];
    __shared__ float sa[4];
    __shared__ float rs[4];
    int lane = t & 31, w = t >> 5;
    if (lane == 0) { sr[w][0] = l[0]; sr[w][1] = l[1]; sr[w][2] = l[2]; sr[w][3] = l[3]; }
    __syncthreads();
    if (t == 0) {
        float L[4];
#pragma unroll
        for (int i = 0; i < 4; ++i)
            L[i] = sr[0][i] + sr[1][i] + sr[2][i] + sr[3][i] + attn_b[i];
        float m = fmaxf(fmaxf(L[0], L[1]), fmaxf(L[2], L[3]));
        float e0 = expf(L[0] - m), e1 = expf(L[1] - m), e2 = expf(L[2] - m), e3 = expf(L[3] - m);
        float s = e0 + e1 + e2 + e3;
        sa[0] = e0 / s; sa[1] = e1 / s; sa[2] = e2 / s; sa[3] = e3 / s;
    }
    __syncthreads();

    float cmb = sa[0] * yr[t] + sa[1] * yr[128 + t] + sa[2] * yr[256 + t] + sa[3] * yr[384 + t];

    float v = cmb;
#pragma unroll
    for (int o = 16; o > 0; o >>= 1) v += __shfl_down_sync(0xffffffffu, v, o);
    if (lane == 0) rs[w] = v;
    __syncthreads();
    float mu = (rs[0] + rs[1] + rs[2] + rs[3]) * (1.0f / 128.0f);
    __syncthreads();

    float d = cmb - mu;
    float v2 = d * d;
#pragma unroll
    for (int o = 16; o > 0; o >>= 1) v2 += __shfl_down_sync(0xffffffffu, v2, o);
    if (lane == 0) rs[w] = v2;
    __syncthreads();
    float var = (rs[0] + rs[1] + rs[2] + rs[3]) * (1.0f / 128.0f);
    float inv = rsqrtf(var + 1e-5f);

    out[(size_t)n * 128 + t] = d * inv * ln_g[t] + ln_b[t];
}

// ---------------- host ----------------
extern "C" void kernel_launch(void* const* d_in, const int* in_sizes, int n_in,
                              void* d_out, int out_size) {
    const float* x      = (const float*)d_in[0];
    const void*  ei     = d_in[1];
    const float* cheb_w = (const float*)d_in[2];
    const float* cheb_b = (const float*)d_in[3];
    const float* attn_w = (const float*)d_in[4];
    const float* attn_b = (const float*)d_in[5];
    const float* ln_g   = (const float*)d_in[6];
    const float* ln_b   = (const float*)d_in[7];
    float*       out    = (float*)d_out;

    int N = in_sizes[0] / 128;
    int E = in_sizes[1] / 2;
    if (N > NMAX) N = NMAX;
    if (E > EMAX) E = EMAX;

    static int smem_set = 0;
    if (!smem_set) {
        cudaFuncSetAttribute(k_gemm_all, cudaFuncAttributeMaxDynamicSharedMemorySize,
                             2 * BUFW * 4);
        smem_set = 1;
    }

    // graph structure build
    k_detect<<<1, 256>>>(ei, E, N);
    k_zero<<<(N + 255) / 256, 256>>>(N);
    k_deg<<<(E + 255) / 256, 256>>>(ei, E, N);
    k_dinv<<<(N + 255) / 256, 256>>>(N);
    int nb = (N + 1023) / 1024;
    k_scan1<<<nb, 1024>>>(N);
    k_scan2<<<1, 32>>>(nb, N);
    k_scan3<<<nb, 1024>>>(N);
    k_scatter<<<(E + 255) / 256, 256>>>(ei, E, N);

    // weight prep + T0 split
    k_wprep<<<NMAT, 256>>>(cheb_w);
    {
        size_t tot = (size_t)N * C;
        k_xconv<<<(unsigned)((tot + 255) / 256), 256>>>(x, N);
    }

    // buffer id schedule: id 3 = x; ids 0..2 = g_T0..g_T2 (ring)
    int id[20];
    id[0] = 3;
    for (int k = 1; k < 20; ++k) id[k] = (k - 1) % 3;

    // Chebyshev recursion, emitting split-bf16 T_k; warp-per-node
    int pgrid = (N * 32 + 255) / 256;
    k_prop<<<pgrid, 256>>>(id[0], id[0], id[1], x, 1.0f, 0.0f, N, 1);
    for (int k = 2; k < 20; ++k)
        k_prop<<<pgrid, 256>>>(id[k - 1], id[k - 2], id[k], x, 2.0f, -1.0f, N, k);

    // fused tensor-core GEMM
    dim3 gg(4, (N + 127) / 128);
    k_gemm_all<<<gg, 256, 2 * BUFW * 4>>>(cheb_b, N);

    k_final<<<N, 128>>>(attn_w, attn_b, ln_g, ln_b, out, N);
}

// round 9
// speedup vs baseline: 3.8194x; 1.0219x over previous
#include <cuda_runtime.h>
#include <cuda_bf16.h>

#define NMAX 50000
#define EMAX 800000
#define C 128
#define TOTK 20
#define NMAT 50

// ---------------- scratch (static device globals; no allocation) ----------------
__device__ int   g_degsrc[NMAX];
__device__ int   g_degdst[NMAX];
__device__ int   g_cursor[NMAX];
__device__ float g_dinv[NMAX];
__device__ int   g_rowptr[NMAX + 1];
__device__ int   g_bsum[64];
__device__ int   g_is64;
__device__ __align__(8) int2 g_epack[EMAX];
__device__ __align__(16) float g_T0[NMAX * C];
__device__ __align__(16) float g_T1[NMAX * C];
__device__ __align__(16) float g_T2[NMAX * C];
__device__ __align__(16) float g_Y[(size_t)NMAX * 512];
__device__ __align__(16) unsigned short g_Th[(size_t)TOTK * NMAX * C];
__device__ __align__(16) unsigned short g_Tl[(size_t)TOTK * NMAX * C];
__device__ __align__(16) unsigned short g_Wh[(size_t)NMAT * C * C];
__device__ __align__(16) unsigned short g_Wl[(size_t)NMAT * C * C];

__device__ __forceinline__ const float* sel_buf(int id, const float* x) {
    switch (id) { case 0: return g_T0; case 1: return g_T1; case 2: return g_T2; default: return x; }
}
__device__ __forceinline__ float* sel_buf_w(int id) {
    switch (id) { case 0: return g_T0; case 1: return g_T1; default: return g_T2; }
}

__device__ __forceinline__ long long load_idx(const void* ei, int is64, size_t pos) {
    if (is64) return ((const long long*)ei)[pos];
    return (long long)((const int*)ei)[pos];
}

// ---------------- dtype detection ----------------
__global__ void k_detect(const void* ei, int E, int N) {
    __shared__ int bad;
    if (threadIdx.x == 0) bad = 0;
    __syncthreads();
    int cnt = min(E, 2048);
    for (int i = threadIdx.x; i < cnt; i += blockDim.x) {
        long long v = ((const long long*)ei)[i];
        if (v < 0 || v >= (long long)N) atomicOr(&bad, 1);
    }
    __syncthreads();
    if (threadIdx.x == 0) g_is64 = bad ? 0 : 1;
}

// ---------------- setup kernels ----------------
__global__ void k_zero(int N) {
    int i = blockIdx.x * blockDim.x + threadIdx.x;
    if (i < N) { g_degsrc[i] = 0; g_degdst[i] = 0; g_cursor[i] = 0; }
}

__global__ void k_deg(const void* __restrict__ ei, int E, int N) {
    int e = blockIdx.x * blockDim.x + threadIdx.x;
    if (e < E) {
        int is64 = g_is64;
        long long s = load_idx(ei, is64, e);
        long long d = load_idx(ei, is64, (size_t)E + e);
        if (s >= 0 && s < N) atomicAdd(&g_degsrc[(int)s], 1);
        if (d >= 0 && d < N) atomicAdd(&g_degdst[(int)d], 1);
    }
}

__global__ void k_dinv(int N) {
    int i = blockIdx.x * blockDim.x + threadIdx.x;
    if (i < N) {
        int d = g_degsrc[i];
        g_dinv[i] = (d > 0) ? rsqrtf((float)d) : 0.0f;
    }
}

__global__ void k_scan1(int N) {
    __shared__ int sh[1024];
    int tid = threadIdx.x;
    int i = blockIdx.x * 1024 + tid;
    int v = (i < N) ? g_degdst[i] : 0;
    sh[tid] = v;
    __syncthreads();
    for (int off = 1; off < 1024; off <<= 1) {
        int t = (tid >= off) ? sh[tid - off] : 0;
        __syncthreads();
        sh[tid] += t;
        __syncthreads();
    }
    if (i < N) g_rowptr[i] = sh[tid] - v;
    if (tid == 1023) g_bsum[blockIdx.x] = sh[1023];
}

__global__ void k_scan2(int nb, int N) {
    if (threadIdx.x == 0 && blockIdx.x == 0) {
        int run = 0;
        for (int b = 0; b < nb; b++) { int v = g_bsum[b]; g_bsum[b] = run; run += v; }
        g_rowptr[N] = run;
    }
}

__global__ void k_scan3(int N) {
    int i = blockIdx.x * 1024 + threadIdx.x;
    if (i < N) g_rowptr[i] += g_bsum[blockIdx.x];
}

__global__ void k_scatter(const void* __restrict__ ei, int E, int N) {
    int e = blockIdx.x * blockDim.x + threadIdx.x;
    if (e < E) {
        int is64 = g_is64;
        long long sl = load_idx(ei, is64, e);
        long long dl = load_idx(ei, is64, (size_t)E + e);
        if (sl < 0 || sl >= N || dl < 0 || dl >= N) return;
        int s = (int)sl, d = (int)dl;
        float w = -g_dinv[s] * g_dinv[d] - 1.0f;
        int pos = g_rowptr[d] + atomicAdd(&g_cursor[d], 1);
        g_epack[pos] = make_int2(s, __float_as_int(w));
    }
}

// ---------------- weight prep: transpose + split into bf16 hi/lo ----------------
__global__ void k_wprep(const float* __restrict__ cheb_w) {
    int mat = blockIdx.x;
    const float* W = cheb_w + (size_t)mat * C * C;
    for (int idx = threadIdx.x; idx < C * C; idx += blockDim.x) {
        int kk = idx >> 7, n = idx & 127;
        float v = W[idx];
        __nv_bfloat16 h = __float2bfloat16(v);
        size_t o = (size_t)mat * C * C + (size_t)n * C + kk;
        g_Wh[o] = __bfloat16_as_ushort(h);
        g_Wl[o] = __bfloat16_as_ushort(__float2bfloat16(v - __bfloat162float(h)));
    }
}

// ---------------- x -> T_0 split ----------------
__global__ void k_xconv(const float* __restrict__ x, int N) {
    size_t i = (size_t)blockIdx.x * blockDim.x + threadIdx.x;
    if (i < (size_t)N * C) {
        float v = x[i];
        __nv_bfloat16 h = __float2bfloat16(v);
        g_Th[i] = __bfloat16_as_ushort(h);
        g_Tl[i] = __bfloat16_as_ushort(__float2bfloat16(v - __bfloat162float(h)));
    }
}

// ---------------- propagation: warp-per-node, float4, packed edges ------------
__global__ void __launch_bounds__(256)
k_prop(int in_id, int sub_id, int out_id, const float* __restrict__ xp,
       float alpha, float beta, int N, int kv) {
    const float4* Tin  = (const float4*)sel_buf(in_id, xp);
    const float4* Tsub = (const float4*)sel_buf(sub_id, xp);
    float4*       Tout = (float4*)sel_buf_w(out_id);

    int node = (blockIdx.x * blockDim.x + threadIdx.x) >> 5;
    if (node >= N) return;
    int lane = threadIdx.x & 31;

    int beg = g_rowptr[node], end = g_rowptr[node + 1];
    float4 acc = make_float4(0.f, 0.f, 0.f, 0.f);

    int j = beg;
    for (; j + 4 <= end; j += 4) {
        int2 e0 = g_epack[j];
        int2 e1 = g_epack[j + 1];
        int2 e2 = g_epack[j + 2];
        int2 e3 = g_epack[j + 3];
        float4 a0 = Tin[(size_t)e0.x * 32 + lane];
        float4 a1 = Tin[(size_t)e1.x * 32 + lane];
        float4 a2 = Tin[(size_t)e2.x * 32 + lane];
        float4 a3 = Tin[(size_t)e3.x * 32 + lane];
        float w0 = __int_as_float(e0.y), w1 = __int_as_float(e1.y);
        float w2 = __int_as_float(e2.y), w3 = __int_as_float(e3.y);
        acc.x += w0 * a0.x; acc.y += w0 * a0.y; acc.z += w0 * a0.z; acc.w += w0 * a0.w;
        acc.x += w1 * a1.x; acc.y += w1 * a1.y; acc.z += w1 * a1.z; acc.w += w1 * a1.w;
        acc.x += w2 * a2.x; acc.y += w2 * a2.y; acc.z += w2 * a2.z; acc.w += w2 * a2.w;
        acc.x += w3 * a3.x; acc.y += w3 * a3.y; acc.z += w3 * a3.z; acc.w += w3 * a3.w;
    }
    for (; j < end; ++j) {
        int2 e = g_epack[j];
        float w = __int_as_float(e.y);
        float4 a = Tin[(size_t)e.x * 32 + lane];
        acc.x += w * a.x; acc.y += w * a.y; acc.z += w * a.z; acc.w += w * a.w;
    }

    float4 sv = Tsub[(size_t)node * 32 + lane];
    float4 v;
    v.x = alpha * acc.x + beta * sv.x;
    v.y = alpha * acc.y + beta * sv.y;
    v.z = alpha * acc.z + beta * sv.z;
    v.w = alpha * acc.w + beta * sv.w;
    Tout[(size_t)node * 32 + lane] = v;

    __nv_bfloat16 hx = __float2bfloat16(v.x), hy = __float2bfloat16(v.y);
    __nv_bfloat16 hz = __float2bfloat16(v.z), hw = __float2bfloat16(v.w);
    ushort4 hi = make_ushort4(__bfloat16_as_ushort(hx), __bfloat16_as_ushort(hy),
                              __bfloat16_as_ushort(hz), __bfloat16_as_ushort(hw));
    ushort4 lo = make_ushort4(
        __bfloat16_as_ushort(__float2bfloat16(v.x - __bfloat162float(hx))),
        __bfloat16_as_ushort(__float2bfloat16(v.y - __bfloat162float(hy))),
        __bfloat16_as_ushort(__float2bfloat16(v.z - __bfloat162float(hz))),
        __bfloat16_as_ushort(__float2bfloat16(v.w - __bfloat162float(hw))));
    size_t o = ((size_t)kv * N + node) * C + lane * 4;
    *(ushort4*)&g_Th[o] = hi;
    *(ushort4*)&g_Tl[o] = lo;
}

// ---------------- fused tensor-core GEMM (mma.sync), per-filter + kv range ------
#define SW 36
#define BUFW (4 * 128 * SW)

__device__ __forceinline__ void mma_bf16(float* c, const unsigned* a, const unsigned* b) {
    asm volatile(
        "mma.sync.aligned.m16n8k16.row.col.f32.bf16.bf16.f32 "
        "{%0,%1,%2,%3}, {%4,%5,%6,%7}, {%8,%9}, {%0,%1,%2,%3};\n"
        : "+f"(c[0]), "+f"(c[1]), "+f"(c[2]), "+f"(c[3])
        : "r"(a[0]), "r"(a[1]), "r"(a[2]), "r"(a[3]), "r"(b[0]), "r"(b[1]));
}

__device__ __forceinline__ void cpa16(unsigned saddr, const void* g, int sz) {
    asm volatile("cp.async.cg.shared.global [%0], [%1], 16, %2;\n"
                 :: "r"(saddr), "l"(g), "r"(sz));
}

__device__ __forceinline__ void gemm_load_chunk(unsigned sbase, int buf, int kv, int mat,
                                                int ch, int tilebase, int N) {
    int t = threadIdx.x;
    const unsigned short* Ah = g_Th + (size_t)kv * N * C;
    const unsigned short* Al = g_Tl + (size_t)kv * N * C;
    const unsigned short* Wh = g_Wh + (size_t)mat * C * C;
    const unsigned short* Wl = g_Wl + (size_t)mat * C * C;
    unsigned b0 = sbase + (unsigned)(buf * BUFW) * 4;
#pragma unroll
    for (int j = 0; j < 4; ++j) {
        int idx = t + j * 256;
        int row = idx >> 3, seg = idx & 7;
        unsigned sm_off = (unsigned)(row * SW + seg * 4) * 4;
        int grow = tilebase + row;
        int ok = (grow < N) ? 16 : 0;
        int growc = (grow < N) ? grow : (N - 1);
        size_t ga = (size_t)growc * C + ch * 64 + seg * 8;
        cpa16(b0 + sm_off,                         Ah + ga, ok);
        cpa16(b0 + (unsigned)(128*SW)*4  + sm_off, Al + ga, ok);
        size_t gw = (size_t)row * C + ch * 64 + seg * 8;
        cpa16(b0 + (unsigned)(2*128*SW)*4 + sm_off, Wh + gw, 16);
        cpa16(b0 + (unsigned)(3*128*SW)*4 + sm_off, Wl + gw, 16);
    }
}

extern __shared__ __align__(16) unsigned sm_u[];

__global__ void __launch_bounds__(256)
k_gemm_all(const float* __restrict__ cheb_b, int N, int f, int kv_lo, int kv_cnt, int accum) {
    int tilebase = blockIdx.x * 128;
    int off = 5 * f * (f + 1) / 2;
    int NC = kv_cnt * 2;

    unsigned sbase = (unsigned)__cvta_generic_to_shared(sm_u);
    int t = threadIdx.x;
    int lane = t & 31, w = t >> 5;
    int warp_m = w & 3, warp_n = w >> 2;
    int g = lane >> 2, tig = lane & 3;

    float acc[2][8][4];
#pragma unroll
    for (int mt = 0; mt < 2; ++mt)
#pragma unroll
        for (int nt = 0; nt < 8; ++nt)
#pragma unroll
            for (int r = 0; r < 4; ++r) acc[mt][nt][r] = 0.0f;

    gemm_load_chunk(sbase, 0, kv_lo, off + kv_lo, 0, tilebase, N);
    asm volatile("cp.async.commit_group;\n" ::: "memory");

    for (int i = 0; i < NC; ++i) {
        if (i + 1 < NC) {
            int kv = kv_lo + ((i + 1) >> 1), ch = (i + 1) & 1;
            gemm_load_chunk(sbase, (i + 1) & 1, kv, off + kv, ch, tilebase, N);
        }
        asm volatile("cp.async.commit_group;\n" ::: "memory");
        if (i + 1 < NC) asm volatile("cp.async.wait_group 1;\n" ::: "memory");
        else            asm volatile("cp.async.wait_group 0;\n" ::: "memory");
        __syncthreads();

        const unsigned* Ah_s = sm_u + (i & 1) * BUFW;
        const unsigned* Al_s = Ah_s + 128 * SW;
        const unsigned* Wh_s = Ah_s + 2 * 128 * SW;
        const unsigned* Wl_s = Ah_s + 3 * 128 * SW;

#pragma unroll
        for (int s = 0; s < 4; ++s) {
            unsigned ah[2][4], al[2][4], bh[8][2], bl[8][2];
#pragma unroll
            for (int mt = 0; mt < 2; ++mt) {
                int w0 = (warp_m * 32 + mt * 16 + g) * SW + s * 8 + tig;
                ah[mt][0] = Ah_s[w0];           ah[mt][1] = Ah_s[w0 + 8 * SW];
                ah[mt][2] = Ah_s[w0 + 4];       ah[mt][3] = Ah_s[w0 + 8 * SW + 4];
                al[mt][0] = Al_s[w0];           al[mt][1] = Al_s[w0 + 8 * SW];
                al[mt][2] = Al_s[w0 + 4];       al[mt][3] = Al_s[w0 + 8 * SW + 4];
            }
#pragma unroll
            for (int nt = 0; nt < 8; ++nt) {
                int w0 = (warp_n * 64 + nt * 8 + g) * SW + s * 8 + tig;
                bh[nt][0] = Wh_s[w0];  bh[nt][1] = Wh_s[w0 + 4];
                bl[nt][0] = Wl_s[w0];  bl[nt][1] = Wl_s[w0 + 4];
            }
#pragma unroll
            for (int mt = 0; mt < 2; ++mt)
#pragma unroll
                for (int nt = 0; nt < 8; ++nt) {
                    mma_bf16(acc[mt][nt], ah[mt], bh[nt]);
                    mma_bf16(acc[mt][nt], ah[mt], bl[nt]);
                    mma_bf16(acc[mt][nt], al[mt], bh[nt]);
                }
        }
        __syncthreads();
    }

#pragma unroll
    for (int mt = 0; mt < 2; ++mt) {
        int r0 = tilebase + warp_m * 32 + mt * 16 + g;
#pragma unroll
        for (int nt = 0; nt < 8; ++nt) {
            int col = warp_n * 64 + nt * 8 + tig * 2;
            size_t gc = (size_t)f * 128 + col;
            if (accum) {
                if (r0 < N) {
                    float2* yp = (float2*)&g_Y[(size_t)r0 * 512 + gc];
                    float2 y = *yp;
                    y.x += acc[mt][nt][0]; y.y += acc[mt][nt][1];
                    *yp = y;
                }
                if (r0 + 8 < N) {
                    float2* yp = (float2*)&g_Y[(size_t)(r0 + 8) * 512 + gc];
                    float2 y = *yp;
                    y.x += acc[mt][nt][2]; y.y += acc[mt][nt][3];
                    *yp = y;
                }
            } else {
                float b0v = cheb_b[f * 128 + col];
                float b1v = cheb_b[f * 128 + col + 1];
                if (r0 < N) {
                    float2 v = make_float2(acc[mt][nt][0] + b0v, acc[mt][nt][1] + b1v);
                    *(float2*)&g_Y[(size_t)r0 * 512 + gc] = v;
                }
                if (r0 + 8 < N) {
                    float2 v = make_float2(acc[mt][nt][2] + b0v, acc[mt][nt][3] + b1v);
                    *(float2*)&g_Y[(size_t)(r0 + 8) * 512 + gc] = v;
                }
            }
        }
    }
}

// ---------------- attention softmax + combine + layernorm ----------------
__global__ void k_final(const float* __restrict__ attn_w, const float* __restrict__ attn_b,
                        const float* __restrict__ ln_g, const float* __restrict__ ln_b,
                        float* __restrict__ out, int N) {
    int n = blockIdx.x, t = threadIdx.x;
    const float* yr = g_Y + (size_t)n * 512;

    float l[4] = {0.f, 0.f, 0.f, 0.f};
    for (int j = t; j < 512; j += 128) {
        float v = yr[j];
        float4 aw = *(const float4*)&attn_w[j * 4];
        l[0] += v * aw.x; l[1] += v * aw.y; l[2] += v * aw.z; l[3] += v * aw.w;
    }
#pragma unroll
    for (int o = 16; o > 0; o >>= 1) {
        l[0] += __shfl_down_sync(0xffffffffu, l[0], o);
        l[1] += __shfl_down_sync(0xffffffffu, l[1], o);
        l[2] += __shfl_down_sync(0xffffffffu, l[2], o);
        l[3] += __shfl_down_sync(0xffffffffu, l[3], o);
    }
    __shared__ float sr[4][4];
    __shared__ float sa[4];
    __shared__ float rs[4];
    int lane = t & 31, w = t >> 5;
    if (lane == 0) { sr[w][0] = l[0]; sr[w][1] = l[1]; sr[w][2] = l[2]; sr[w][3] = l[3]; }
    __syncthreads();
    if (t == 0) {
        float L[4];
#pragma unroll
        for (int i = 0; i < 4; ++i)
            L[i] = sr[0][i] + sr[1][i] + sr[2][i] + sr[3][i] + attn_b[i];
        float m = fmaxf(fmaxf(L[0], L[1]), fmaxf(L[2], L[3]));
        float e0 = expf(L[0] - m), e1 = expf(L[1] - m), e2 = expf(L[2] - m), e3 = expf(L[3] - m);
        float s = e0 + e1 + e2 + e3;
        sa[0] = e0 / s; sa[1] = e1 / s; sa[2] = e2 / s; sa[3] = e3 / s;
    }
    __syncthreads();

    float cmb = sa[0] * yr[t] + sa[1] * yr[128 + t] + sa[2] * yr[256 + t] + sa[3] * yr[384 + t];

    float v = cmb;
#pragma unroll
    for (int o = 16; o > 0; o >>= 1) v += __shfl_down_sync(0xffffffffu, v, o);
    if (lane == 0) rs[w] = v;
    __syncthreads();
    float mu = (rs[0] + rs[1] + rs[2] + rs[3]) * (1.0f / 128.0f);
    __syncthreads();

    float d = cmb - mu;
    float v2 = d * d;
#pragma unroll
    for (int o = 16; o > 0; o >>= 1) v2 += __shfl_down_sync(0xffffffffu, v2, o);
    if (lane == 0) rs[w] = v2;
    __syncthreads();
    float var = (rs[0] + rs[1] + rs[2] + rs[3]) * (1.0f / 128.0f);
    float inv = rsqrtf(var + 1e-5f);

    out[(size_t)n * 128 + t] = d * inv * ln_g[t] + ln_b[t];
}

// ---------------- host ----------------
extern "C" void kernel_launch(void* const* d_in, const int* in_sizes, int n_in,
                              void* d_out, int out_size) {
    const float* x      = (const float*)d_in[0];
    const void*  ei     = d_in[1];
    const float* cheb_w = (const float*)d_in[2];
    const float* cheb_b = (const float*)d_in[3];
    const float* attn_w = (const float*)d_in[4];
    const float* attn_b = (const float*)d_in[5];
    const float* ln_g   = (const float*)d_in[6];
    const float* ln_b   = (const float*)d_in[7];
    float*       out    = (float*)d_out;

    int N = in_sizes[0] / 128;
    int E = in_sizes[1] / 2;
    if (N > NMAX) N = NMAX;
    if (E > EMAX) E = EMAX;

    static int inited = 0;
    static cudaStream_t s2;
    static cudaEvent_t ev[5];
    if (!inited) {
        cudaFuncSetAttribute(k_gemm_all, cudaFuncAttributeMaxDynamicSharedMemorySize,
                             2 * BUFW * 4);
        cudaStreamCreateWithFlags(&s2, cudaStreamNonBlocking);
        for (int i = 0; i < 5; ++i)
            cudaEventCreateWithFlags(&ev[i], cudaEventDisableTiming);
        inited = 1;
    }

    int tiles = (N + 127) / 128;

    // graph structure build (stream 0)
    k_detect<<<1, 256>>>(ei, E, N);
    k_zero<<<(N + 255) / 256, 256>>>(N);
    k_deg<<<(E + 255) / 256, 256>>>(ei, E, N);
    k_dinv<<<(N + 255) / 256, 256>>>(N);
    int nb = (N + 1023) / 1024;
    k_scan1<<<nb, 1024>>>(N);
    k_scan2<<<1, 32>>>(nb, N);
    k_scan3<<<nb, 1024>>>(N);
    k_scatter<<<(E + 255) / 256, 256>>>(ei, E, N);

    // weight prep + T0 split
    k_wprep<<<NMAT, 256>>>(cheb_w);
    {
        size_t tot = (size_t)N * C;
        k_xconv<<<(unsigned)((tot + 255) / 256), 256>>>(x, N);
    }

    // buffer id schedule: id 3 = x; ids 0..2 = g_T0..g_T2 (ring)
    int id[20];
    id[0] = 3;
    for (int k = 1; k < 20; ++k) id[k] = (k - 1) % 3;

    int pgrid = (N * 32 + 255) / 256;

    // prop 1..4, then release f0 GEMM
    k_prop<<<pgrid, 256>>>(id[0], id[0], id[1], x, 1.0f, 0.0f, N, 1);
    for (int k = 2; k <= 4; ++k)
        k_prop<<<pgrid, 256>>>(id[k - 1], id[k - 2], id[k], x, 2.0f, -1.0f, N, k);
    cudaEventRecord(ev[0], 0);
    cudaStreamWaitEvent(s2, ev[0], 0);
    k_gemm_all<<<tiles, 256, 2 * BUFW * 4, s2>>>(cheb_b, N, 0, 0, 5, 0);

    // prop 5..9, release f1
    for (int k = 5; k <= 9; ++k)
        k_prop<<<pgrid, 256>>>(id[k - 1], id[k - 2], id[k], x, 2.0f, -1.0f, N, k);
    cudaEventRecord(ev[1], 0);
    cudaStreamWaitEvent(s2, ev[1], 0);
    k_gemm_all<<<tiles, 256, 2 * BUFW * 4, s2>>>(cheb_b, N, 1, 0, 10, 0);

    // prop 10..14, release f2 and f3 part 1 (kv 0..14)
    for (int k = 10; k <= 14; ++k)
        k_prop<<<pgrid, 256>>>(id[k - 1], id[k - 2], id[k], x, 2.0f, -1.0f, N, k);
    cudaEventRecord(ev[2], 0);
    cudaStreamWaitEvent(s2, ev[2], 0);
    k_gemm_all<<<tiles, 256, 2 * BUFW * 4, s2>>>(cheb_b, N, 2, 0, 15, 0);
    k_gemm_all<<<tiles, 256, 2 * BUFW * 4, s2>>>(cheb_b, N, 3, 0, 15, 0);

    // prop 15..19, release f3 part 2 (kv 15..19, accumulate)
    for (int k = 15; k <= 19; ++k)
        k_prop<<<pgrid, 256>>>(id[k - 1], id[k - 2], id[k], x, 2.0f, -1.0f, N, k);
    cudaEventRecord(ev[3], 0);
    cudaStreamWaitEvent(s2, ev[3], 0);
    k_gemm_all<<<tiles, 256, 2 * BUFW * 4, s2>>>(cheb_b, N, 3, 15, 5, 1);

    // join: final depends on all GEMMs
    cudaEventRecord(ev[4], s2);
    cudaStreamWaitEvent(0, ev[4], 0);
    k_final<<<N, 128>>>(attn_w, attn_b, ln_g, ln_b, out, N);
}

// round 10
// speedup vs baseline: 4.2947x; 1.1244x over previous
#include <cuda_runtime.h>
#include <cuda_bf16.h>

#define NMAX 50000
#define EMAX 800000
#define C 128
#define TOTK 20
#define NMAT 50

// ---------------- scratch (static device globals; no allocation) ----------------
__device__ int   g_degsrc[NMAX];
__device__ int   g_degdst[NMAX];
__device__ int   g_cursor[NMAX];
__device__ float g_dinv[NMAX];
__device__ int   g_rowptr[NMAX + 1];
__device__ int   g_bsum[64];
__device__ int   g_is64;
__device__ __align__(8) int2 g_epack[EMAX];
__device__ __align__(16) float g_Y[(size_t)NMAX * 512];
// persistent fp32 Chebyshev bases: [k][node][c]  (512 MB)
__device__ __align__(16) float g_Tf[(size_t)TOTK * NMAX * C];
// tf32-rounded transposed weights: [mat][n][k]
__device__ __align__(16) float g_Wt[(size_t)NMAT * C * C];

__device__ __forceinline__ long long load_idx(const void* ei, int is64, size_t pos) {
    if (is64) return ((const long long*)ei)[pos];
    return (long long)((const int*)ei)[pos];
}

__device__ __forceinline__ unsigned cvt_tf32(float f) {
    unsigned r; asm("cvt.rna.tf32.f32 %0, %1;" : "=r"(r) : "f"(f)); return r;
}

// ---------------- dtype detection ----------------
__global__ void k_detect(const void* ei, int E, int N) {
    __shared__ int bad;
    if (threadIdx.x == 0) bad = 0;
    __syncthreads();
    int cnt = min(E, 2048);
    for (int i = threadIdx.x; i < cnt; i += blockDim.x) {
        long long v = ((const long long*)ei)[i];
        if (v < 0 || v >= (long long)N) atomicOr(&bad, 1);
    }
    __syncthreads();
    if (threadIdx.x == 0) g_is64 = bad ? 0 : 1;
}

// ---------------- setup kernels ----------------
__global__ void k_zero(int N) {
    int i = blockIdx.x * blockDim.x + threadIdx.x;
    if (i < N) { g_degsrc[i] = 0; g_degdst[i] = 0; g_cursor[i] = 0; }
}

__global__ void k_deg(const void* __restrict__ ei, int E, int N) {
    int e = blockIdx.x * blockDim.x + threadIdx.x;
    if (e < E) {
        int is64 = g_is64;
        long long s = load_idx(ei, is64, e);
        long long d = load_idx(ei, is64, (size_t)E + e);
        if (s >= 0 && s < N) atomicAdd(&g_degsrc[(int)s], 1);
        if (d >= 0 && d < N) atomicAdd(&g_degdst[(int)d], 1);
    }
}

__global__ void k_dinv(int N) {
    int i = blockIdx.x * blockDim.x + threadIdx.x;
    if (i < N) {
        int d = g_degsrc[i];
        g_dinv[i] = (d > 0) ? rsqrtf((float)d) : 0.0f;
    }
}

__global__ void k_scan1(int N) {
    __shared__ int sh[1024];
    int tid = threadIdx.x;
    int i = blockIdx.x * 1024 + tid;
    int v = (i < N) ? g_degdst[i] : 0;
    sh[tid] = v;
    __syncthreads();
    for (int off = 1; off < 1024; off <<= 1) {
        int t = (tid >= off) ? sh[tid - off] : 0;
        __syncthreads();
        sh[tid] += t;
        __syncthreads();
    }
    if (i < N) g_rowptr[i] = sh[tid] - v;
    if (tid == 1023) g_bsum[blockIdx.x] = sh[1023];
}

__global__ void k_scan2(int nb, int N) {
    if (threadIdx.x == 0 && blockIdx.x == 0) {
        int run = 0;
        for (int b = 0; b < nb; b++) { int v = g_bsum[b]; g_bsum[b] = run; run += v; }
        g_rowptr[N] = run;
    }
}

__global__ void k_scan3(int N) {
    int i = blockIdx.x * 1024 + threadIdx.x;
    if (i < N) g_rowptr[i] += g_bsum[blockIdx.x];
}

__global__ void k_scatter(const void* __restrict__ ei, int E, int N) {
    int e = blockIdx.x * blockDim.x + threadIdx.x;
    if (e < E) {
        int is64 = g_is64;
        long long sl = load_idx(ei, is64, e);
        long long dl = load_idx(ei, is64, (size_t)E + e);
        if (sl < 0 || sl >= N || dl < 0 || dl >= N) return;
        int s = (int)sl, d = (int)dl;
        float w = -g_dinv[s] * g_dinv[d] - 1.0f;
        int pos = g_rowptr[d] + atomicAdd(&g_cursor[d], 1);
        g_epack[pos] = make_int2(s, __float_as_int(w));
    }
}

// ---------------- weight prep: transpose + tf32 round ----------------
__global__ void k_wprep(const float* __restrict__ cheb_w) {
    int mat = blockIdx.x;
    const float* W = cheb_w + (size_t)mat * C * C;
    for (int idx = threadIdx.x; idx < C * C; idx += blockDim.x) {
        int kk = idx >> 7, n = idx & 127;
        unsigned r = cvt_tf32(W[idx]);
        g_Wt[(size_t)mat * C * C + (size_t)n * C + kk] = __uint_as_float(r);
    }
}

// ---------------- x -> g_Tf[0] ----------------
__global__ void k_xcopy(const float* __restrict__ x, int N) {
    size_t i = (size_t)blockIdx.x * blockDim.x + threadIdx.x;
    if (i < (size_t)N * C / 4) ((float4*)g_Tf)[i] = ((const float4*)x)[i];
}

// ---------------- propagation: warp-per-node, float4, packed edges ------------
__global__ void __launch_bounds__(256)
k_prop(int kv, float alpha, float beta, int N) {
    size_t S = (size_t)N * C;
    const float4* Tin  = (const float4*)(g_Tf + (size_t)(kv - 1) * S);
    const float4* Tsub = (const float4*)(g_Tf + (size_t)(kv >= 2 ? kv - 2 : 0) * S);
    float4*       Tout = (float4*)(g_Tf + (size_t)kv * S);

    int node = (blockIdx.x * blockDim.x + threadIdx.x) >> 5;
    if (node >= N) return;
    int lane = threadIdx.x & 31;

    int beg = g_rowptr[node], end = g_rowptr[node + 1];
    float4 acc = make_float4(0.f, 0.f, 0.f, 0.f);

    int j = beg;
    for (; j + 4 <= end; j += 4) {
        int2 e0 = g_epack[j];
        int2 e1 = g_epack[j + 1];
        int2 e2 = g_epack[j + 2];
        int2 e3 = g_epack[j + 3];
        float4 a0 = Tin[(size_t)e0.x * 32 + lane];
        float4 a1 = Tin[(size_t)e1.x * 32 + lane];
        float4 a2 = Tin[(size_t)e2.x * 32 + lane];
        float4 a3 = Tin[(size_t)e3.x * 32 + lane];
        float w0 = __int_as_float(e0.y), w1 = __int_as_float(e1.y);
        float w2 = __int_as_float(e2.y), w3 = __int_as_float(e3.y);
        acc.x += w0 * a0.x; acc.y += w0 * a0.y; acc.z += w0 * a0.z; acc.w += w0 * a0.w;
        acc.x += w1 * a1.x; acc.y += w1 * a1.y; acc.z += w1 * a1.z; acc.w += w1 * a1.w;
        acc.x += w2 * a2.x; acc.y += w2 * a2.y; acc.z += w2 * a2.z; acc.w += w2 * a2.w;
        acc.x += w3 * a3.x; acc.y += w3 * a3.y; acc.z += w3 * a3.z; acc.w += w3 * a3.w;
    }
    for (; j < end; ++j) {
        int2 e = g_epack[j];
        float w = __int_as_float(e.y);
        float4 a = Tin[(size_t)e.x * 32 + lane];
        acc.x += w * a.x; acc.y += w * a.y; acc.z += w * a.z; acc.w += w * a.w;
    }

    float4 sv = Tsub[(size_t)node * 32 + lane];
    float4 v;
    v.x = alpha * acc.x + beta * sv.x;
    v.y = alpha * acc.y + beta * sv.y;
    v.z = alpha * acc.z + beta * sv.z;
    v.w = alpha * acc.w + beta * sv.w;
    Tout[(size_t)node * 32 + lane] = v;
}

// ---------------- tf32 tensor-core GEMM, per-filter + kv range ------------------
#define SWF 68                       // padded row stride in floats (64 + 4)
#define CHUNKF (128 * SWF)           // floats per buffer
#define GEMM_SMEM_B (4 * CHUNKF * 4) // A0,A1,W0,W1

__device__ __forceinline__ void mma_tf32(float* c, const unsigned* a, const unsigned* b) {
    asm volatile(
        "mma.sync.aligned.m16n8k8.row.col.f32.tf32.tf32.f32 "
        "{%0,%1,%2,%3}, {%4,%5,%6,%7}, {%8,%9}, {%0,%1,%2,%3};\n"
        : "+f"(c[0]), "+f"(c[1]), "+f"(c[2]), "+f"(c[3])
        : "r"(a[0]), "r"(a[1]), "r"(a[2]), "r"(a[3]), "r"(b[0]), "r"(b[1]));
}

__device__ __forceinline__ void cpa16(unsigned saddr, const void* g, int sz) {
    asm volatile("cp.async.cg.shared.global [%0], [%1], 16, %2;\n"
                 :: "r"(saddr), "l"(g), "r"(sz));
}

__device__ __forceinline__ void gemm_load_chunk(unsigned sbase, int buf, int kv, int mat,
                                                int ch, int tilebase, int N) {
    int t = threadIdx.x;
    const float* A = g_Tf + (size_t)kv * N * C + ch * 64;
    const float* W = g_Wt + (size_t)mat * C * C + ch * 64;
    unsigned ab = sbase + (unsigned)buf * (CHUNKF * 4);
    unsigned wb = sbase + (unsigned)(2 + buf) * (CHUNKF * 4);
#pragma unroll
    for (int j = 0; j < 8; ++j) {
        int idx = t + j * 256;
        int row = idx >> 4, seg = idx & 15;
        unsigned so = (unsigned)(row * SWF + seg * 4) * 4;
        int grow = tilebase + row;
        if (grow > N - 1) grow = N - 1;
        cpa16(ab + so, A + (size_t)grow * C + seg * 4, 16);
        cpa16(wb + so, W + (size_t)row * C + seg * 4, 16);
    }
}

extern __shared__ __align__(16) float sm_f[];

__global__ void __launch_bounds__(256)
k_gemm_all(const float* __restrict__ cheb_b, int N, int f, int kv_lo, int kv_cnt, int accum) {
    int tilebase = blockIdx.x * 128;
    int off = 5 * f * (f + 1) / 2;
    int NC = kv_cnt * 2;

    unsigned sbase = (unsigned)__cvta_generic_to_shared(sm_f);
    int t = threadIdx.x;
    int lane = t & 31, w = t >> 5;
    int warp_m = w & 3, warp_n = w >> 2;     // 4 x 2 warps; warp tile 32m x 64n
    int g = lane >> 2, tig = lane & 3;

    float acc[2][8][4];
#pragma unroll
    for (int mt = 0; mt < 2; ++mt)
#pragma unroll
        for (int nt = 0; nt < 8; ++nt)
#pragma unroll
            for (int r = 0; r < 4; ++r) acc[mt][nt][r] = 0.0f;

    gemm_load_chunk(sbase, 0, kv_lo, off + kv_lo, 0, tilebase, N);
    asm volatile("cp.async.commit_group;\n" ::: "memory");

    for (int i = 0; i < NC; ++i) {
        if (i + 1 < NC) {
            int kv = kv_lo + ((i + 1) >> 1), ch = (i + 1) & 1;
            gemm_load_chunk(sbase, (i + 1) & 1, kv, off + kv, ch, tilebase, N);
        }
        asm volatile("cp.async.commit_group;\n" ::: "memory");
        if (i + 1 < NC) asm volatile("cp.async.wait_group 1;\n" ::: "memory");
        else            asm volatile("cp.async.wait_group 0;\n" ::: "memory");
        __syncthreads();

        const float* As = sm_f + (i & 1) * CHUNKF;
        const float* Ws = sm_f + (2 + (i & 1)) * CHUNKF;

#pragma unroll
        for (int ks = 0; ks < 8; ++ks) {
            unsigned a[2][4], b[8][2];
#pragma unroll
            for (int mt = 0; mt < 2; ++mt) {
                int R = warp_m * 32 + mt * 16;
                int kc = ks * 8 + tig;
                a[mt][0] = cvt_tf32(As[(R + g)     * SWF + kc]);
                a[mt][1] = cvt_tf32(As[(R + 8 + g) * SWF + kc]);
                a[mt][2] = cvt_tf32(As[(R + g)     * SWF + kc + 4]);
                a[mt][3] = cvt_tf32(As[(R + 8 + g) * SWF + kc + 4]);
            }
#pragma unroll
            for (int nt = 0; nt < 8; ++nt) {
                int n = warp_n * 64 + nt * 8 + g;
                int kc = ks * 8 + tig;
                b[nt][0] = __float_as_uint(Ws[n * SWF + kc]);
                b[nt][1] = __float_as_uint(Ws[n * SWF + kc + 4]);
            }
#pragma unroll
            for (int mt = 0; mt < 2; ++mt)
#pragma unroll
                for (int nt = 0; nt < 8; ++nt)
                    mma_tf32(acc[mt][nt], a[mt], b[nt]);
        }
        __syncthreads();
    }

#pragma unroll
    for (int mt = 0; mt < 2; ++mt) {
        int r0 = tilebase + warp_m * 32 + mt * 16 + g;
#pragma unroll
        for (int nt = 0; nt < 8; ++nt) {
            int col = warp_n * 64 + nt * 8 + tig * 2;
            size_t gc = (size_t)f * 128 + col;
            if (accum) {
                if (r0 < N) {
                    float2* yp = (float2*)&g_Y[(size_t)r0 * 512 + gc];
                    float2 y = *yp;
                    y.x += acc[mt][nt][0]; y.y += acc[mt][nt][1];
                    *yp = y;
                }
                if (r0 + 8 < N) {
                    float2* yp = (float2*)&g_Y[(size_t)(r0 + 8) * 512 + gc];
                    float2 y = *yp;
                    y.x += acc[mt][nt][2]; y.y += acc[mt][nt][3];
                    *yp = y;
                }
            } else {
                float b0v = cheb_b[f * 128 + col];
                float b1v = cheb_b[f * 128 + col + 1];
                if (r0 < N) {
                    float2 v = make_float2(acc[mt][nt][0] + b0v, acc[mt][nt][1] + b1v);
                    *(float2*)&g_Y[(size_t)r0 * 512 + gc] = v;
                }
                if (r0 + 8 < N) {
                    float2 v = make_float2(acc[mt][nt][2] + b0v, acc[mt][nt][3] + b1v);
                    *(float2*)&g_Y[(size_t)(r0 + 8) * 512 + gc] = v;
                }
            }
        }
    }
}

// ---------------- attention softmax + combine + layernorm ----------------
__global__ void k_final(const float* __restrict__ attn_w, const float* __restrict__ attn_b,
                        const float* __restrict__ ln_g, const float* __restrict__ ln_b,
                        float* __restrict__ out, int N) {
    int n = blockIdx.x, t = threadIdx.x;
    const float* yr = g_Y + (size_t)n * 512;

    float l[4] = {0.f, 0.f, 0.f, 0.f};
    for (int j = t; j < 512; j += 128) {
        float v = yr[j];
        float4 aw = *(const float4*)&attn_w[j * 4];
        l[0] += v * aw.x; l[1] += v * aw.y; l[2] += v * aw.z; l[3] += v * aw.w;
    }
#pragma unroll
    for (int o = 16; o > 0; o >>= 1) {
        l[0] += __shfl_down_sync(0xffffffffu, l[0], o);
        l[1] += __shfl_down_sync(0xffffffffu, l[1], o);
        l[2] += __shfl_down_sync(0xffffffffu, l[2], o);
        l[3] += __shfl_down_sync(0xffffffffu, l[3], o);
    }
    __shared__ float sr[4][4];
    __shared__ float sa[4];
    __shared__ float rs[4];
    int lane = t & 31, w = t >> 5;
    if (lane == 0) { sr[w][0] = l[0]; sr[w][1] = l[1]; sr[w][2] = l[2]; sr[w][3] = l[3]; }
    __syncthreads();
    if (t == 0) {
        float L[4];
#pragma unroll
        for (int i = 0; i < 4; ++i)
            L[i] = sr[0][i] + sr[1][i] + sr[2][i] + sr[3][i] + attn_b[i];
        float m = fmaxf(fmaxf(L[0], L[1]), fmaxf(L[2], L[3]));
        float e0 = expf(L[0] - m), e1 = expf(L[1] - m), e2 = expf(L[2] - m), e3 = expf(L[3] - m);
        float s = e0 + e1 + e2 + e3;
        sa[0] = e0 / s; sa[1] = e1 / s; sa[2] = e2 / s; sa[3] = e3 / s;
    }
    __syncthreads();

    float cmb = sa[0] * yr[t] + sa[1] * yr[128 + t] + sa[2] * yr[256 + t] + sa[3] * yr[384 + t];

    float v = cmb;
#pragma unroll
    for (int o = 16; o > 0; o >>= 1) v += __shfl_down_sync(0xffffffffu, v, o);
    if (lane == 0) rs[w] = v;
    __syncthreads();
    float mu = (rs[0] + rs[1] + rs[2] + rs[3]) * (1.0f / 128.0f);
    __syncthreads();

    float d = cmb - mu;
    float v2 = d * d;
#pragma unroll
    for (int o = 16; o > 0; o >>= 1) v2 += __shfl_down_sync(0xffffffffu, v2, o);
    if (lane == 0) rs[w] = v2;
    __syncthreads();
    float var = (rs[0] + rs[1] + rs[2] + rs[3]) * (1.0f / 128.0f);
    float inv = rsqrtf(var + 1e-5f);

    out[(size_t)n * 128 + t] = d * inv * ln_g[t] + ln_b[t];
}

// ---------------- host ----------------
extern "C" void kernel_launch(void* const* d_in, const int* in_sizes, int n_in,
                              void* d_out, int out_size) {
    const float* x      = (const float*)d_in[0];
    const void*  ei     = d_in[1];
    const float* cheb_w = (const float*)d_in[2];
    const float* cheb_b = (const float*)d_in[3];
    const float* attn_w = (const float*)d_in[4];
    const float* attn_b = (const float*)d_in[5];
    const float* ln_g   = (const float*)d_in[6];
    const float* ln_b   = (const float*)d_in[7];
    float*       out    = (float*)d_out;

    int N = in_sizes[0] / 128;
    int E = in_sizes[1] / 2;
    if (N > NMAX) N = NMAX;
    if (E > EMAX) E = EMAX;

    static int inited = 0;
    static cudaStream_t s2;
    static cudaEvent_t ev[5];
    if (!inited) {
        cudaFuncSetAttribute(k_gemm_all, cudaFuncAttributeMaxDynamicSharedMemorySize,
                             GEMM_SMEM_B);
        cudaStreamCreateWithFlags(&s2, cudaStreamNonBlocking);
        for (int i = 0; i < 5; ++i)
            cudaEventCreateWithFlags(&ev[i], cudaEventDisableTiming);
        inited = 1;
    }

    int tiles = (N + 127) / 128;

    // graph structure build (stream 0)
    k_detect<<<1, 256>>>(ei, E, N);
    k_zero<<<(N + 255) / 256, 256>>>(N);
    k_deg<<<(E + 255) / 256, 256>>>(ei, E, N);
    k_dinv<<<(N + 255) / 256, 256>>>(N);
    int nb = (N + 1023) / 1024;
    k_scan1<<<nb, 1024>>>(N);
    k_scan2<<<1, 32>>>(nb, N);
    k_scan3<<<nb, 1024>>>(N);
    k_scatter<<<(E + 255) / 256, 256>>>(ei, E, N);

    // weight prep + T0 copy
    k_wprep<<<NMAT, 256>>>(cheb_w);
    {
        size_t tot = (size_t)N * C / 4;
        k_xcopy<<<(unsigned)((tot + 255) / 256), 256>>>(x, N);
    }

    int pgrid = (N * 32 + 255) / 256;

    // prop 1..4, then release f0 GEMM
    k_prop<<<pgrid, 256>>>(1, 1.0f, 0.0f, N);
    for (int k = 2; k <= 4; ++k)
        k_prop<<<pgrid, 256>>>(k, 2.0f, -1.0f, N);
    cudaEventRecord(ev[0], 0);
    cudaStreamWaitEvent(s2, ev[0], 0);
    k_gemm_all<<<tiles, 256, GEMM_SMEM_B, s2>>>(cheb_b, N, 0, 0, 5, 0);

    // prop 5..9, release f1
    for (int k = 5; k <= 9; ++k)
        k_prop<<<pgrid, 256>>>(k, 2.0f, -1.0f, N);
    cudaEventRecord(ev[1], 0);
    cudaStreamWaitEvent(s2, ev[1], 0);
    k_gemm_all<<<tiles, 256, GEMM_SMEM_B, s2>>>(cheb_b, N, 1, 0, 10, 0);

    // prop 10..14, release f2 and f3 part 1 (kv 0..14)
    for (int k = 10; k <= 14; ++k)
        k_prop<<<pgrid, 256>>>(k, 2.0f, -1.0f, N);
    cudaEventRecord(ev[2], 0);
    cudaStreamWaitEvent(s2, ev[2], 0);
    k_gemm_all<<<tiles, 256, GEMM_SMEM_B, s2>>>(cheb_b, N, 2, 0, 15, 0);
    k_gemm_all<<<tiles, 256, GEMM_SMEM_B, s2>>>(cheb_b, N, 3, 0, 15, 0);

    // prop 15..19, release f3 part 2 (kv 15..19, accumulate)
    for (int k = 15; k <= 19; ++k)
        k_prop<<<pgrid, 256>>>(k, 2.0f, -1.0f, N);
    cudaEventRecord(ev[3], 0);
    cudaStreamWaitEvent(s2, ev[3], 0);
    k_gemm_all<<<tiles, 256, GEMM_SMEM_B, s2>>>(cheb_b, N, 3, 15, 5, 1);

    // join: final depends on all GEMMs
    cudaEventRecord(ev[4], s2);
    cudaStreamWaitEvent(0, ev[4], 0);
    k_final<<<N, 128>>>(attn_w, attn_b, ln_g, ln_b, out, N);
}

// round 11
// speedup vs baseline: 4.4655x; 1.0398x over previous
#include <cuda_runtime.h>
#include <cuda_bf16.h>

#define NMAX 50000
#define EMAX 800000
#define C 128
#define TOTK 20
#define NMAT 50

// ---------------- scratch (static device globals; no allocation) ----------------
__device__ int   g_degsrc[NMAX];
__device__ int   g_degdst[NMAX];
__device__ int   g_cursor[NMAX];
__device__ float g_dinv[NMAX];
__device__ int   g_rowptr[NMAX + 1];
__device__ int   g_bsum[64];
__device__ int   g_is64;
__device__ __align__(8) int2 g_epack[EMAX];
__device__ __align__(16) float g_Y[(size_t)NMAX * 512];
// persistent fp32 Chebyshev bases: [k][node][c]; slot 0 unused (x used directly)
__device__ __align__(16) float g_Tf[(size_t)TOTK * NMAX * C];
// tf32-rounded transposed weights: [mat][n][k]
__device__ __align__(16) float g_Wt[(size_t)NMAT * C * C];

__device__ __forceinline__ long long load_idx(const void* ei, int is64, size_t pos) {
    if (is64) return ((const long long*)ei)[pos];
    return (long long)((const int*)ei)[pos];
}

__device__ __forceinline__ unsigned cvt_tf32(float f) {
    unsigned r; asm("cvt.rna.tf32.f32 %0, %1;" : "=r"(r) : "f"(f)); return r;
}

// ---------------- dtype detection ----------------
__global__ void k_detect(const void* ei, int E, int N) {
    __shared__ int bad;
    if (threadIdx.x == 0) bad = 0;
    __syncthreads();
    int cnt = min(E, 2048);
    for (int i = threadIdx.x; i < cnt; i += blockDim.x) {
        long long v = ((const long long*)ei)[i];
        if (v < 0 || v >= (long long)N) atomicOr(&bad, 1);
    }
    __syncthreads();
    if (threadIdx.x == 0) g_is64 = bad ? 0 : 1;
}

// ---------------- setup kernels ----------------
__global__ void k_zero(int N) {
    int i = blockIdx.x * blockDim.x + threadIdx.x;
    if (i < N) { g_degsrc[i] = 0; g_degdst[i] = 0; g_cursor[i] = 0; }
}

__global__ void k_deg(const void* __restrict__ ei, int E, int N) {
    int e = blockIdx.x * blockDim.x + threadIdx.x;
    if (e < E) {
        int is64 = g_is64;
        long long s = load_idx(ei, is64, e);
        long long d = load_idx(ei, is64, (size_t)E + e);
        if (s >= 0 && s < N) atomicAdd(&g_degsrc[(int)s], 1);
        if (d >= 0 && d < N) atomicAdd(&g_degdst[(int)d], 1);
    }
}

__global__ void k_dinv(int N) {
    int i = blockIdx.x * blockDim.x + threadIdx.x;
    if (i < N) {
        int d = g_degsrc[i];
        g_dinv[i] = (d > 0) ? rsqrtf((float)d) : 0.0f;
    }
}

__global__ void k_scan1(int N) {
    __shared__ int sh[1024];
    int tid = threadIdx.x;
    int i = blockIdx.x * 1024 + tid;
    int v = (i < N) ? g_degdst[i] : 0;
    sh[tid] = v;
    __syncthreads();
    for (int off = 1; off < 1024; off <<= 1) {
        int t = (tid >= off) ? sh[tid - off] : 0;
        __syncthreads();
        sh[tid] += t;
        __syncthreads();
    }
    if (i < N) g_rowptr[i] = sh[tid] - v;
    if (tid == 1023) g_bsum[blockIdx.x] = sh[1023];
}

__global__ void k_scan2(int nb, int N) {
    if (threadIdx.x == 0 && blockIdx.x == 0) {
        int run = 0;
        for (int b = 0; b < nb; b++) { int v = g_bsum[b]; g_bsum[b] = run; run += v; }
        g_rowptr[N] = run;
    }
}

__global__ void k_scan3(int N) {
    int i = blockIdx.x * 1024 + threadIdx.x;
    if (i < N) g_rowptr[i] += g_bsum[blockIdx.x];
}

__global__ void k_scatter(const void* __restrict__ ei, int E, int N) {
    int e = blockIdx.x * blockDim.x + threadIdx.x;
    if (e < E) {
        int is64 = g_is64;
        long long sl = load_idx(ei, is64, e);
        long long dl = load_idx(ei, is64, (size_t)E + e);
        if (sl < 0 || sl >= N || dl < 0 || dl >= N) return;
        int s = (int)sl, d = (int)dl;
        float w = -g_dinv[s] * g_dinv[d] - 1.0f;
        int pos = g_rowptr[d] + atomicAdd(&g_cursor[d], 1);
        g_epack[pos] = make_int2(s, __float_as_int(w));
    }
}

// ---------------- weight prep: transpose + tf32 round ----------------
__global__ void k_wprep(const float* __restrict__ cheb_w) {
    int mat = blockIdx.x;
    const float* W = cheb_w + (size_t)mat * C * C;
    for (int idx = threadIdx.x; idx < C * C; idx += blockDim.x) {
        int kk = idx >> 7, n = idx & 127;
        unsigned r = cvt_tf32(W[idx]);
        g_Wt[(size_t)mat * C * C + (size_t)n * C + kk] = __uint_as_float(r);
    }
}

// ---------------- basis pointer: kv==0 -> x, else g_Tf slot ----------------
__device__ __forceinline__ const float* basis(int kv, const float* x, int N) {
    return (kv == 0) ? x : (g_Tf + (size_t)kv * N * C);
}

// ---------------- propagation: warp-per-node, float4, packed edges ------------
__global__ void __launch_bounds__(256)
k_prop(int kv, const float* __restrict__ x, float alpha, float beta, int N) {
    const float4* Tin  = (const float4*)basis(kv - 1, x, N);
    const float4* Tsub = (const float4*)basis(kv >= 2 ? kv - 2 : 0, x, N);
    float4*       Tout = (float4*)(g_Tf + (size_t)kv * N * C);

    int node = (blockIdx.x * blockDim.x + threadIdx.x) >> 5;
    if (node >= N) return;
    int lane = threadIdx.x & 31;

    int beg = g_rowptr[node], end = g_rowptr[node + 1];
    float4 acc = make_float4(0.f, 0.f, 0.f, 0.f);

    int j = beg;
    for (; j + 4 <= end; j += 4) {
        int2 e0 = g_epack[j];
        int2 e1 = g_epack[j + 1];
        int2 e2 = g_epack[j + 2];
        int2 e3 = g_epack[j + 3];
        float4 a0 = Tin[(size_t)e0.x * 32 + lane];
        float4 a1 = Tin[(size_t)e1.x * 32 + lane];
        float4 a2 = Tin[(size_t)e2.x * 32 + lane];
        float4 a3 = Tin[(size_t)e3.x * 32 + lane];
        float w0 = __int_as_float(e0.y), w1 = __int_as_float(e1.y);
        float w2 = __int_as_float(e2.y), w3 = __int_as_float(e3.y);
        acc.x += w0 * a0.x; acc.y += w0 * a0.y; acc.z += w0 * a0.z; acc.w += w0 * a0.w;
        acc.x += w1 * a1.x; acc.y += w1 * a1.y; acc.z += w1 * a1.z; acc.w += w1 * a1.w;
        acc.x += w2 * a2.x; acc.y += w2 * a2.y; acc.z += w2 * a2.z; acc.w += w2 * a2.w;
        acc.x += w3 * a3.x; acc.y += w3 * a3.y; acc.z += w3 * a3.z; acc.w += w3 * a3.w;
    }
    for (; j < end; ++j) {
        int2 e = g_epack[j];
        float w = __int_as_float(e.y);
        float4 a = Tin[(size_t)e.x * 32 + lane];
        acc.x += w * a.x; acc.y += w * a.y; acc.z += w * a.z; acc.w += w * a.w;
    }

    float4 sv = Tsub[(size_t)node * 32 + lane];
    float4 v;
    v.x = alpha * acc.x + beta * sv.x;
    v.y = alpha * acc.y + beta * sv.y;
    v.z = alpha * acc.z + beta * sv.z;
    v.w = alpha * acc.w + beta * sv.w;
    Tout[(size_t)node * 32 + lane] = v;
}

// ---------------- tf32 tensor-core GEMM, per-filter + kv range ------------------
#define SWF 68                       // padded row stride in floats (64 + 4)
#define CHUNKF (128 * SWF)           // floats per buffer
#define GEMM_SMEM_B (4 * CHUNKF * 4) // A0,A1,W0,W1

__device__ __forceinline__ void mma_tf32(float* c, const unsigned* a, const unsigned* b) {
    asm volatile(
        "mma.sync.aligned.m16n8k8.row.col.f32.tf32.tf32.f32 "
        "{%0,%1,%2,%3}, {%4,%5,%6,%7}, {%8,%9}, {%0,%1,%2,%3};\n"
        : "+f"(c[0]), "+f"(c[1]), "+f"(c[2]), "+f"(c[3])
        : "r"(a[0]), "r"(a[1]), "r"(a[2]), "r"(a[3]), "r"(b[0]), "r"(b[1]));
}

__device__ __forceinline__ void cpa16(unsigned saddr, const void* g, int sz) {
    asm volatile("cp.async.cg.shared.global [%0], [%1], 16, %2;\n"
                 :: "r"(saddr), "l"(g), "r"(sz));
}

__device__ __forceinline__ void gemm_load_chunk(unsigned sbase, int buf, int kv, int mat,
                                                int ch, int tilebase, int N,
                                                const float* __restrict__ x) {
    int t = threadIdx.x;
    const float* A = basis(kv, x, N) + ch * 64;
    const float* W = g_Wt + (size_t)mat * C * C + ch * 64;
    unsigned ab = sbase + (unsigned)buf * (CHUNKF * 4);
    unsigned wb = sbase + (unsigned)(2 + buf) * (CHUNKF * 4);
#pragma unroll
    for (int j = 0; j < 8; ++j) {
        int idx = t + j * 256;
        int row = idx >> 4, seg = idx & 15;
        unsigned so = (unsigned)(row * SWF + seg * 4) * 4;
        int grow = tilebase + row;
        if (grow > N - 1) grow = N - 1;
        cpa16(ab + so, A + (size_t)grow * C + seg * 4, 16);
        cpa16(wb + so, W + (size_t)row * C + seg * 4, 16);
    }
}

extern __shared__ __align__(16) float sm_f[];

__global__ void __launch_bounds__(256)
k_gemm_all(const float* __restrict__ cheb_b, const float* __restrict__ x,
           int N, int f, int kv_lo, int kv_cnt, int accum) {
    int tilebase = blockIdx.x * 128;
    int off = 5 * f * (f + 1) / 2;
    int NC = kv_cnt * 2;

    unsigned sbase = (unsigned)__cvta_generic_to_shared(sm_f);
    int t = threadIdx.x;
    int lane = t & 31, w = t >> 5;
    int warp_m = w & 3, warp_n = w >> 2;
    int g = lane >> 2, tig = lane & 3;

    float acc[2][8][4];
#pragma unroll
    for (int mt = 0; mt < 2; ++mt)
#pragma unroll
        for (int nt = 0; nt < 8; ++nt)
#pragma unroll
            for (int r = 0; r < 4; ++r) acc[mt][nt][r] = 0.0f;

    gemm_load_chunk(sbase, 0, kv_lo, off + kv_lo, 0, tilebase, N, x);
    asm volatile("cp.async.commit_group;\n" ::: "memory");

    for (int i = 0; i < NC; ++i) {
        if (i + 1 < NC) {
            int kv = kv_lo + ((i + 1) >> 1), ch = (i + 1) & 1;
            gemm_load_chunk(sbase, (i + 1) & 1, kv, off + kv, ch, tilebase, N, x);
        }
        asm volatile("cp.async.commit_group;\n" ::: "memory");
        if (i + 1 < NC) asm volatile("cp.async.wait_group 1;\n" ::: "memory");
        else            asm volatile("cp.async.wait_group 0;\n" ::: "memory");
        __syncthreads();

        const float* As = sm_f + (i & 1) * CHUNKF;
        const float* Ws = sm_f + (2 + (i & 1)) * CHUNKF;

#pragma unroll
        for (int ks = 0; ks < 8; ++ks) {
            unsigned a[2][4], b[8][2];
#pragma unroll
            for (int mt = 0; mt < 2; ++mt) {
                int R = warp_m * 32 + mt * 16;
                int kc = ks * 8 + tig;
                a[mt][0] = cvt_tf32(As[(R + g)     * SWF + kc]);
                a[mt][1] = cvt_tf32(As[(R + 8 + g) * SWF + kc]);
                a[mt][2] = cvt_tf32(As[(R + g)     * SWF + kc + 4]);
                a[mt][3] = cvt_tf32(As[(R + 8 + g) * SWF + kc + 4]);
            }
#pragma unroll
            for (int nt = 0; nt < 8; ++nt) {
                int n = warp_n * 64 + nt * 8 + g;
                int kc = ks * 8 + tig;
                b[nt][0] = __float_as_uint(Ws[n * SWF + kc]);
                b[nt][1] = __float_as_uint(Ws[n * SWF + kc + 4]);
            }
#pragma unroll
            for (int mt = 0; mt < 2; ++mt)
#pragma unroll
                for (int nt = 0; nt < 8; ++nt)
                    mma_tf32(acc[mt][nt], a[mt], b[nt]);
        }
        __syncthreads();
    }

#pragma unroll
    for (int mt = 0; mt < 2; ++mt) {
        int r0 = tilebase + warp_m * 32 + mt * 16 + g;
#pragma unroll
        for (int nt = 0; nt < 8; ++nt) {
            int col = warp_n * 64 + nt * 8 + tig * 2;
            size_t gc = (size_t)f * 128 + col;
            if (accum) {
                if (r0 < N) {
                    float2* yp = (float2*)&g_Y[(size_t)r0 * 512 + gc];
                    float2 y = *yp;
                    y.x += acc[mt][nt][0]; y.y += acc[mt][nt][1];
                    *yp = y;
                }
                if (r0 + 8 < N) {
                    float2* yp = (float2*)&g_Y[(size_t)(r0 + 8) * 512 + gc];
                    float2 y = *yp;
                    y.x += acc[mt][nt][2]; y.y += acc[mt][nt][3];
                    *yp = y;
                }
            } else {
                float b0v = cheb_b[f * 128 + col];
                float b1v = cheb_b[f * 128 + col + 1];
                if (r0 < N) {
                    float2 v = make_float2(acc[mt][nt][0] + b0v, acc[mt][nt][1] + b1v);
                    *(float2*)&g_Y[(size_t)r0 * 512 + gc] = v;
                }
                if (r0 + 8 < N) {
                    float2 v = make_float2(acc[mt][nt][2] + b0v, acc[mt][nt][3] + b1v);
                    *(float2*)&g_Y[(size_t)(r0 + 8) * 512 + gc] = v;
                }
            }
        }
    }
}

// ---------------- attention softmax + combine + layernorm (warp-per-node) -------
__global__ void __launch_bounds__(256)
k_final(const float* __restrict__ attn_w, const float* __restrict__ attn_b,
        const float* __restrict__ ln_g, const float* __restrict__ ln_b,
        float* __restrict__ out, int N) {
    int node = (blockIdx.x * blockDim.x + threadIdx.x) >> 5;
    if (node >= N) return;
    int lane = threadIdx.x & 31;

    const float4* yr = (const float4*)(g_Y + (size_t)node * 512);
    const float4* aw = (const float4*)attn_w;

    float4 v[4];
    float l0 = 0.f, l1 = 0.f, l2 = 0.f, l3 = 0.f;
#pragma unroll
    for (int f = 0; f < 4; ++f) {
        v[f] = yr[f * 32 + lane];
        int jb = f * 128 + lane * 4;
        float4 a0 = aw[jb], a1 = aw[jb + 1], a2 = aw[jb + 2], a3 = aw[jb + 3];
        l0 += v[f].x * a0.x + v[f].y * a1.x + v[f].z * a2.x + v[f].w * a3.x;
        l1 += v[f].x * a0.y + v[f].y * a1.y + v[f].z * a2.y + v[f].w * a3.y;
        l2 += v[f].x * a0.z + v[f].y * a1.z + v[f].z * a2.z + v[f].w * a3.z;
        l3 += v[f].x * a0.w + v[f].y * a1.w + v[f].z * a2.w + v[f].w * a3.w;
    }
#pragma unroll
    for (int o = 16; o > 0; o >>= 1) {
        l0 += __shfl_xor_sync(0xffffffffu, l0, o);
        l1 += __shfl_xor_sync(0xffffffffu, l1, o);
        l2 += __shfl_xor_sync(0xffffffffu, l2, o);
        l3 += __shfl_xor_sync(0xffffffffu, l3, o);
    }
    l0 += attn_b[0]; l1 += attn_b[1]; l2 += attn_b[2]; l3 += attn_b[3];
    float m = fmaxf(fmaxf(l0, l1), fmaxf(l2, l3));
    float e0 = expf(l0 - m), e1 = expf(l1 - m), e2 = expf(l2 - m), e3 = expf(l3 - m);
    float s = e0 + e1 + e2 + e3;
    float a0 = e0 / s, a1 = e1 / s, a2 = e2 / s, a3 = e3 / s;

    float4 cmb;
    cmb.x = a0 * v[0].x + a1 * v[1].x + a2 * v[2].x + a3 * v[3].x;
    cmb.y = a0 * v[0].y + a1 * v[1].y + a2 * v[2].y + a3 * v[3].y;
    cmb.z = a0 * v[0].z + a1 * v[1].z + a2 * v[2].z + a3 * v[3].z;
    cmb.w = a0 * v[0].w + a1 * v[1].w + a2 * v[2].w + a3 * v[3].w;

    float ssum = cmb.x + cmb.y + cmb.z + cmb.w;
#pragma unroll
    for (int o = 16; o > 0; o >>= 1) ssum += __shfl_xor_sync(0xffffffffu, ssum, o);
    float mu = ssum * (1.0f / 128.0f);

    float4 d = make_float4(cmb.x - mu, cmb.y - mu, cmb.z - mu, cmb.w - mu);
    float vs = d.x * d.x + d.y * d.y + d.z * d.z + d.w * d.w;
#pragma unroll
    for (int o = 16; o > 0; o >>= 1) vs += __shfl_xor_sync(0xffffffffu, vs, o);
    float var = vs * (1.0f / 128.0f);
    float inv = rsqrtf(var + 1e-5f);

    float4 gg = ((const float4*)ln_g)[lane];
    float4 bb = ((const float4*)ln_b)[lane];
    float4 o4;
    o4.x = d.x * inv * gg.x + bb.x;
    o4.y = d.y * inv * gg.y + bb.y;
    o4.z = d.z * inv * gg.z + bb.z;
    o4.w = d.w * inv * gg.w + bb.w;
    ((float4*)out)[(size_t)node * 32 + lane] = o4;
}

// ---------------- host ----------------
extern "C" void kernel_launch(void* const* d_in, const int* in_sizes, int n_in,
                              void* d_out, int out_size) {
    const float* x      = (const float*)d_in[0];
    const void*  ei     = d_in[1];
    const float* cheb_w = (const float*)d_in[2];
    const float* cheb_b = (const float*)d_in[3];
    const float* attn_w = (const float*)d_in[4];
    const float* attn_b = (const float*)d_in[5];
    const float* ln_g   = (const float*)d_in[6];
    const float* ln_b   = (const float*)d_in[7];
    float*       out    = (float*)d_out;

    int N = in_sizes[0] / 128;
    int E = in_sizes[1] / 2;
    if (N > NMAX) N = NMAX;
    if (E > EMAX) E = EMAX;

    static int inited = 0;
    static cudaStream_t s2, s3;
    static cudaEvent_t ev[6];
    if (!inited) {
        cudaFuncSetAttribute(k_gemm_all, cudaFuncAttributeMaxDynamicSharedMemorySize,
                             GEMM_SMEM_B);
        cudaStreamCreateWithFlags(&s2, cudaStreamNonBlocking);
        cudaStreamCreateWithFlags(&s3, cudaStreamNonBlocking);
        for (int i = 0; i < 6; ++i)
            cudaEventCreateWithFlags(&ev[i], cudaEventDisableTiming);
        inited = 1;
    }

    int tiles = (N + 127) / 128;

    // graph structure build (stream 0)
    k_detect<<<1, 256>>>(ei, E, N);
    k_zero<<<(N + 255) / 256, 256>>>(N);
    k_deg<<<(E + 255) / 256, 256>>>(ei, E, N);
    k_dinv<<<(N + 255) / 256, 256>>>(N);
    int nb = (N + 1023) / 1024;
    k_scan1<<<nb, 1024>>>(N);
    k_scan2<<<1, 32>>>(nb, N);
    k_scan3<<<nb, 1024>>>(N);
    k_scatter<<<(E + 255) / 256, 256>>>(ei, E, N);

    // weight prep (no x copy needed; x used directly as T0)
    k_wprep<<<NMAT, 256>>>(cheb_w);

    int pgrid = (N * 32 + 255) / 256;

    // prop 1..4, then release f0 GEMM (s2)
    k_prop<<<pgrid, 256>>>(1, x, 1.0f, 0.0f, N);
    for (int k = 2; k <= 4; ++k)
        k_prop<<<pgrid, 256>>>(k, x, 2.0f, -1.0f, N);
    cudaEventRecord(ev[0], 0);
    cudaStreamWaitEvent(s2, ev[0], 0);
    k_gemm_all<<<tiles, 256, GEMM_SMEM_B, s2>>>(cheb_b, x, N, 0, 0, 5, 0);

    // prop 5..9, release f1 (s3)
    for (int k = 5; k <= 9; ++k)
        k_prop<<<pgrid, 256>>>(k, x, 2.0f, -1.0f, N);
    cudaEventRecord(ev[1], 0);
    cudaStreamWaitEvent(s3, ev[1], 0);
    k_gemm_all<<<tiles, 256, GEMM_SMEM_B, s3>>>(cheb_b, x, N, 1, 0, 10, 0);

    // prop 10..14, release f2 (s2) and f3 part 1 (s3) concurrently
    for (int k = 10; k <= 14; ++k)
        k_prop<<<pgrid, 256>>>(k, x, 2.0f, -1.0f, N);
    cudaEventRecord(ev[2], 0);
    cudaStreamWaitEvent(s2, ev[2], 0);
    cudaStreamWaitEvent(s3, ev[2], 0);
    k_gemm_all<<<tiles, 256, GEMM_SMEM_B, s2>>>(cheb_b, x, N, 2, 0, 15, 0);
    k_gemm_all<<<tiles, 256, GEMM_SMEM_B, s3>>>(cheb_b, x, N, 3, 0, 15, 0);

    // prop 15..19, release f3 part 2 (s3; accumulates after part 1)
    for (int k = 15; k <= 19; ++k)
        k_prop<<<pgrid, 256>>>(k, x, 2.0f, -1.0f, N);
    cudaEventRecord(ev[3], 0);
    cudaStreamWaitEvent(s3, ev[3], 0);
    k_gemm_all<<<tiles, 256, GEMM_SMEM_B, s3>>>(cheb_b, x, N, 3, 15, 5, 1);

    // join: final depends on all GEMMs
    cudaEventRecord(ev[4], s2);
    cudaEventRecord(ev[5], s3);
    cudaStreamWaitEvent(0, ev[4], 0);
    cudaStreamWaitEvent(0, ev[5], 0);
    k_final<<<pgrid, 256>>>(attn_w, attn_b, ln_g, ln_b, out, N);
}